// round 1
// baseline (speedup 1.0000x reference)
#include <cuda_runtime.h>

#define BATCH 8
#define RESO 64
#define DIMC 256
#define NH 8
#define HD 32
#define WIN 512
#define NWTOT 64   // BATCH * 8 stripe windows
#define LTOK 4096  // RESO*RESO

// Scratch (allocation-free rule: __device__ globals)
__device__ float g_x[(size_t)NWTOT * WIN * DIMC];     // attn output (+lepe added)
__device__ float g_lepe[(size_t)NWTOT * WIN * DIMC];  // depthwise-conv LePE

// ---------------------------------------------------------------------------
// LePE: depthwise 3x3 conv (cross-correlation, pad=1) over each [64 x 8]
// window image of V, per channel. out[(w,t),c]
// ---------------------------------------------------------------------------
__global__ __launch_bounds__(256) void lepe_kernel(const float* __restrict__ v,
                                                   const float* __restrict__ cw,
                                                   const float* __restrict__ cb) {
    int t = blockIdx.x;          // token in window 0..511
    int w = blockIdx.y;          // window 0..63
    int c = threadIdx.x;         // channel 0..255
    int b = w >> 3, j = w & 7;
    int r = t >> 3, c2 = t & 7;
    float acc = cb[c];
    #pragma unroll
    for (int dr = -1; dr <= 1; dr++) {
        int rr = r + dr;
        if (rr < 0 || rr >= RESO) continue;
        #pragma unroll
        for (int dc = -1; dc <= 1; dc++) {
            int cc = c2 + dc;
            if (cc < 0 || cc >= 8) continue;   // pad relative to the 64x8 window
            int l = rr * RESO + j * 8 + cc;
            acc += v[((size_t)b * LTOK + l) * DIMC + c] *
                   cw[c * 9 + (dr + 1) * 3 + (dc + 1)];
        }
    }
    g_lepe[((size_t)w * WIN + t) * DIMC + c] = acc;
}

// ---------------------------------------------------------------------------
// Attention: one block = (window w, head n, query-half z). K,V [512x32] fp32
// in 128KB dynamic smem. Each of 256 threads owns one query row, online
// softmax over all 512 keys. Mask: only window j==7, groups c2<4 vs c2>=4.
// Adds LePE at the store.
// ---------------------------------------------------------------------------
__global__ __launch_bounds__(256) void attn_kernel(const float* __restrict__ qkv,
                                                   const float* __restrict__ scale_p) {
    extern __shared__ float smem[];
    float* Ks = smem;                 // [512][32]
    float* Vs = smem + WIN * HD;      // [512][32]
    int w = blockIdx.x;               // 0..63
    int n = blockIdx.y;               // 0..7
    int b = w >> 3, j = w & 7;
    const float* kp = qkv + (size_t)BATCH * LTOK * DIMC;
    const float* vp = kp + (size_t)BATCH * LTOK * DIMC;
    int tid = threadIdx.x;

    // Cooperative K/V load: 4096 float4 pairs
    for (int i = tid; i < WIN * 8; i += 256) {
        int s = i >> 3, f4 = i & 7;
        int rs = s >> 3, cs = s & 7;
        size_t base = ((size_t)b * LTOK + rs * RESO + j * 8 + cs) * DIMC + n * HD + f4 * 4;
        *(float4*)(Ks + s * HD + f4 * 4) = *(const float4*)(kp + base);
        *(float4*)(Vs + s * HD + f4 * 4) = *(const float4*)(vp + base);
    }
    __syncthreads();

    float scale = scale_p[0];
    int t = blockIdx.z * 256 + tid;
    int r = t >> 3, c2 = t & 7;
    const float* qrow = qkv + ((size_t)b * LTOK + r * RESO + j * 8 + c2) * DIMC + n * HD;
    float qv[HD];
    #pragma unroll
    for (int d4 = 0; d4 < 8; d4++) {
        float4 q4 = *(const float4*)(qrow + d4 * 4);
        qv[d4 * 4 + 0] = q4.x * scale;
        qv[d4 * 4 + 1] = q4.y * scale;
        qv[d4 * 4 + 2] = q4.z * scale;
        qv[d4 * 4 + 3] = q4.w * scale;
    }

    float m = -1e30f, lsum = 0.f;
    float acc[HD];
    #pragma unroll
    for (int d = 0; d < HD; d++) acc[d] = 0.f;
    bool maskwin = (j == 7);
    bool tg = (c2 < 4);

    for (int s = 0; s < WIN; s++) {
        const float* kr = Ks + s * HD;
        float dot = 0.f;
        #pragma unroll
        for (int d = 0; d < HD; d++) dot += qv[d] * kr[d];
        if (maskwin && (((s & 7) < 4) != tg)) dot -= 100.f;
        if (dot > m) {                         // rare rescale branch
            float corr = __expf(m - dot);
            m = dot;
            lsum *= corr;
            #pragma unroll
            for (int d = 0; d < HD; d++) acc[d] *= corr;
        }
        float p = __expf(dot - m);
        lsum += p;
        const float* vr = Vs + s * HD;
        #pragma unroll
        for (int d = 0; d < HD; d++) acc[d] += p * vr[d];
    }

    float inv = 1.f / lsum;
    size_t oi = ((size_t)w * WIN + t) * DIMC + n * HD;
    #pragma unroll
    for (int d = 0; d < HD; d++) g_x[oi + d] = acc[d] * inv + g_lepe[oi + d];
}

// ---------------------------------------------------------------------------
// Projection: C[m, c] = sum_k (g_x[m,k]) * W[c,k] + bias[c], scattered back
// to [B, L, DIM] image order. Tiled 64x64x16 SIMT GEMM, 4x4 per thread.
// ---------------------------------------------------------------------------
__global__ __launch_bounds__(256) void proj_kernel(const float* __restrict__ W,
                                                   const float* __restrict__ bias,
                                                   float* __restrict__ out) {
    __shared__ float As[16][64];
    __shared__ float Bs[16][64];
    int tid = threadIdx.x;
    int tx = tid & 15, ty = tid >> 4;
    int m0 = blockIdx.y * 64;
    int n0 = blockIdx.x * 64;
    int lrow = tid >> 2;            // 0..63
    int lk4 = (tid & 3) << 2;       // 0,4,8,12
    float acc[4][4] = {};

    for (int k0 = 0; k0 < DIMC; k0 += 16) {
        float4 av = *(const float4*)&g_x[(size_t)(m0 + lrow) * DIMC + k0 + lk4];
        float4 bv = *(const float4*)&W[(size_t)(n0 + lrow) * DIMC + k0 + lk4];
        __syncthreads();
        As[lk4 + 0][lrow] = av.x; As[lk4 + 1][lrow] = av.y;
        As[lk4 + 2][lrow] = av.z; As[lk4 + 3][lrow] = av.w;
        Bs[lk4 + 0][lrow] = bv.x; Bs[lk4 + 1][lrow] = bv.y;
        Bs[lk4 + 2][lrow] = bv.z; Bs[lk4 + 3][lrow] = bv.w;
        __syncthreads();
        #pragma unroll
        for (int kk = 0; kk < 16; kk++) {
            float a[4], bb[4];
            #pragma unroll
            for (int i = 0; i < 4; i++) a[i] = As[kk][ty * 4 + i];
            #pragma unroll
            for (int i2 = 0; i2 < 4; i2++) bb[i2] = Bs[kk][tx * 4 + i2];
            #pragma unroll
            for (int i = 0; i < 4; i++)
                #pragma unroll
                for (int i2 = 0; i2 < 4; i2++)
                    acc[i][i2] += a[i] * bb[i2];
        }
    }

    #pragma unroll
    for (int i = 0; i < 4; i++) {
        int mrow = m0 + ty * 4 + i;
        int wI = mrow >> 9, t = mrow & 511;
        int bI = wI >> 3, jI = wI & 7;
        int rI = t >> 3, c2I = t & 7;
        size_t obase = ((size_t)bI * LTOK + rI * RESO + jI * 8 + c2I) * DIMC + n0 + tx * 4;
        #pragma unroll
        for (int i2 = 0; i2 < 4; i2++)
            out[obase + i2] = acc[i][i2] + bias[n0 + tx * 4 + i2];
    }
}

// ---------------------------------------------------------------------------
extern "C" void kernel_launch(void* const* d_in, const int* in_sizes, int n_in,
                              void* d_out, int out_size) {
    (void)in_sizes; (void)n_in; (void)out_size;
    const float* qkv    = (const float*)d_in[0];
    const float* scale  = (const float*)d_in[1];
    const float* proj_w = (const float*)d_in[2];
    const float* proj_b = (const float*)d_in[3];
    const float* conv_w = (const float*)d_in[4];
    const float* conv_b = (const float*)d_in[5];
    float* out = (float*)d_out;

    const float* v = qkv + 2ULL * BATCH * LTOK * DIMC;

    lepe_kernel<<<dim3(WIN, NWTOT), 256>>>(v, conv_w, conv_b);

    static const size_t attn_smem = 2ULL * WIN * HD * sizeof(float);  // 128KB
    cudaFuncSetAttribute(attn_kernel, cudaFuncAttributeMaxDynamicSharedMemorySize,
                         (int)attn_smem);
    attn_kernel<<<dim3(NWTOT, NH, 2), 256, attn_smem>>>(qkv, scale);

    proj_kernel<<<dim3(DIMC / 64, (NWTOT * WIN) / 64), 256>>>(proj_w, proj_b, out);
}

// round 3
// speedup vs baseline: 3.9200x; 3.9200x over previous
#include <cuda_runtime.h>
#include <cuda_fp16.h>
#include <cstdint>

#define BATCH 8
#define RESO 64
#define DIMC 256
#define NH 8
#define HD 32
#define WIN 512
#define NWTOT 64
#define LTOK 4096

// ---------------------------------------------------------------------------
// Scratch (__device__ globals: allocation-free rule)
// ---------------------------------------------------------------------------
__device__ float  g_lepe[(size_t)NWTOT * WIN * DIMC];
__device__ __half g_xhi[(size_t)NWTOT * WIN * DIMC];
__device__ __half g_xlo[(size_t)NWTOT * WIN * DIMC];

// ---------------------------------------------------------------------------
// Helpers
// ---------------------------------------------------------------------------
__device__ __forceinline__ uint32_t ldu32(const __half* p) {
    return *reinterpret_cast<const uint32_t*>(p);
}
__device__ __forceinline__ uint32_t packh2(float x, float y) {
    __half2 h = __floats2half2_rn(x, y);
    return *reinterpret_cast<uint32_t*>(&h);
}
__device__ __forceinline__ void mma16816(float d[4], const uint32_t a[4],
                                         const uint32_t b[2]) {
    asm volatile(
        "mma.sync.aligned.m16n8k16.row.col.f32.f16.f16.f32 "
        "{%0,%1,%2,%3}, {%4,%5,%6,%7}, {%8,%9}, {%0,%1,%2,%3};\n"
        : "+f"(d[0]), "+f"(d[1]), "+f"(d[2]), "+f"(d[3])
        : "r"(a[0]), "r"(a[1]), "r"(a[2]), "r"(a[3]), "r"(b[0]), "r"(b[1]));
}
// split f into hi(fp16) + lo(fp16 of residual); store half2 pairs
__device__ __forceinline__ void split_store4(__half* hi, __half* lo, float4 f) {
    __half h0 = __float2half_rn(f.x), h1 = __float2half_rn(f.y);
    __half h2 = __float2half_rn(f.z), h3 = __float2half_rn(f.w);
    *(__half2*)hi       = __halves2half2(h0, h1);
    *(__half2*)(hi + 2) = __halves2half2(h2, h3);
    *(__half2*)lo = __halves2half2(__float2half_rn(f.x - __half2float(h0)),
                                   __float2half_rn(f.y - __half2float(h1)));
    *(__half2*)(lo + 2) = __halves2half2(__float2half_rn(f.z - __half2float(h2)),
                                         __float2half_rn(f.w - __half2float(h3)));
}
__device__ __forceinline__ void split_store2(__half* hi, __half* lo, float x0, float x1) {
    __half h0 = __float2half_rn(x0), h1 = __float2half_rn(x1);
    *(__half2*)hi = __halves2half2(h0, h1);
    *(__half2*)lo = __halves2half2(__float2half_rn(x0 - __half2float(h0)),
                                   __float2half_rn(x1 - __half2float(h1)));
}

// ---------------------------------------------------------------------------
// LePE: depthwise 3x3 conv on V windows
// ---------------------------------------------------------------------------
__global__ __launch_bounds__(256) void lepe_kernel(const float* __restrict__ v,
                                                   const float* __restrict__ cw,
                                                   const float* __restrict__ cb) {
    int t = blockIdx.x, w = blockIdx.y, c = threadIdx.x;
    int b = w >> 3, j = w & 7;
    int r = t >> 3, c2 = t & 7;
    float acc = cb[c];
    #pragma unroll
    for (int dr = -1; dr <= 1; dr++) {
        int rr = r + dr;
        if (rr < 0 || rr >= RESO) continue;
        #pragma unroll
        for (int dc = -1; dc <= 1; dc++) {
            int cc = c2 + dc;
            if (cc < 0 || cc >= 8) continue;
            int l = rr * RESO + j * 8 + cc;
            acc += v[((size_t)b * LTOK + l) * DIMC + c] *
                   cw[c * 9 + (dr + 1) * 3 + (dc + 1)];
        }
    }
    g_lepe[((size_t)w * WIN + t) * DIMC + c] = acc;
}

// ---------------------------------------------------------------------------
// HMMA flash attention. CTA = (window, head). 8 warps x 64 query rows.
// smem halves: Qhi/Qlo/Khi/Klo [512][40], Vt [32][520]
// ---------------------------------------------------------------------------
#define QHI 0
#define QLO (512 * 40)
#define KHI (2 * 512 * 40)
#define KLO (3 * 512 * 40)
#define VTO (4 * 512 * 40)
#define ATTN_SMEM_BYTES ((4 * 512 * 40 + 32 * 520) * 2)

__global__ __launch_bounds__(256, 1) void attn_hmma(const float* __restrict__ qkv,
                                                    const float* __restrict__ scale_p) {
    extern __shared__ __half sm[];
    const int tid = threadIdx.x;
    const int w = blockIdx.x, n = blockIdx.y;
    const int b = w >> 3, j = w & 7;
    const float scale = scale_p[0];
    const float* qp = qkv;
    const float* kp = qkv + (size_t)BATCH * LTOK * DIMC;
    const float* vp = kp + (size_t)BATCH * LTOK * DIMC;

    // ---- fill Q/K (hi+lo split) ----
    for (int i = tid; i < 512 * 8; i += 256) {
        int s = i >> 3, f4 = i & 7;
        int rs = s >> 3, cs = s & 7;
        size_t gbase = ((size_t)b * LTOK + rs * RESO + j * 8 + cs) * DIMC + n * HD + f4 * 4;
        float4 qf = *(const float4*)(qp + gbase);
        float4 kf = *(const float4*)(kp + gbase);
        qf.x *= scale; qf.y *= scale; qf.z *= scale; qf.w *= scale;
        int so = s * 40 + f4 * 4;
        split_store4(sm + QHI + so, sm + QLO + so, qf);
        split_store4(sm + KHI + so, sm + KLO + so, kf);
    }
    // ---- fill Vt [d][key] ----
    for (int i = tid; i < 512 * 16; i += 256) {
        int key = i >> 4, dp = i & 15;
        int rs = key >> 3, cs = key & 7;
        const float* src = vp + ((size_t)b * LTOK + rs * RESO + j * 8 + cs) * DIMC + n * HD + dp * 2;
        float2 f = *(const float2*)src;
        sm[VTO + (dp * 2) * 520 + key]     = __float2half_rn(f.x);
        sm[VTO + (dp * 2 + 1) * 520 + key] = __float2half_rn(f.y);
    }
    __syncthreads();

    const int wid = tid >> 5, lane = tid & 31;
    const int g = lane >> 2, t2 = (lane & 3) * 2;
    const int m0 = wid * 64;
    const bool mzero = (j == 7) && ((g < 4) != ((lane & 3) < 2));

    float O[4][4][4];
    float lsl[4], lsh[4];
    #pragma unroll
    for (int mt = 0; mt < 4; mt++) {
        lsl[mt] = 0.f; lsh[mt] = 0.f;
        #pragma unroll
        for (int nt = 0; nt < 4; nt++)
            #pragma unroll
            for (int e = 0; e < 4; e++) O[mt][nt][e] = 0.f;
    }

    for (int c = 0; c < 16; c++) {
        const int k0 = c * 32;
        float S[4][4][4];
        #pragma unroll
        for (int mt = 0; mt < 4; mt++)
            #pragma unroll
            for (int nt = 0; nt < 4; nt++)
                #pragma unroll
                for (int e = 0; e < 4; e++) S[mt][nt][e] = 0.f;

        // ---- 3-pass split QK^T ----
        #pragma unroll
        for (int pass = 0; pass < 3; pass++) {
            const __half* Ab = sm + (pass == 2 ? QLO : QHI);
            const __half* Bb = sm + (pass == 1 ? KLO : KHI);
            uint32_t a[4][2][4];
            #pragma unroll
            for (int mt = 0; mt < 4; mt++)
                #pragma unroll
                for (int ks = 0; ks < 2; ks++) {
                    const __half* p0 = Ab + (m0 + mt * 16 + g) * 40 + ks * 16 + t2;
                    a[mt][ks][0] = ldu32(p0);
                    a[mt][ks][1] = ldu32(p0 + 8 * 40);
                    a[mt][ks][2] = ldu32(p0 + 8);
                    a[mt][ks][3] = ldu32(p0 + 8 * 40 + 8);
                }
            uint32_t bb[4][2][2];
            #pragma unroll
            for (int nt = 0; nt < 4; nt++)
                #pragma unroll
                for (int ks = 0; ks < 2; ks++) {
                    const __half* p0 = Bb + (k0 + nt * 8 + g) * 40 + ks * 16 + t2;
                    bb[nt][ks][0] = ldu32(p0);
                    bb[nt][ks][1] = ldu32(p0 + 8);
                }
            #pragma unroll
            for (int mt = 0; mt < 4; mt++)
                #pragma unroll
                for (int nt = 0; nt < 4; nt++)
                    #pragma unroll
                    for (int ks = 0; ks < 2; ks++)
                        mma16816(S[mt][nt], a[mt][ks], bb[nt][ks]);
        }

        // ---- V B-fragments for this key chunk ----
        uint32_t vb[2][4][2];
        #pragma unroll
        for (int kv = 0; kv < 2; kv++)
            #pragma unroll
            for (int ntd = 0; ntd < 4; ntd++) {
                const __half* p0 = sm + VTO + (ntd * 8 + g) * 520 + k0 + kv * 16 + t2;
                vb[kv][ntd][0] = ldu32(p0);
                vb[kv][ntd][1] = ldu32(p0 + 8);
            }

        // ---- softmax exp + PV (P reused as A-fragment) ----
        #pragma unroll
        for (int mt = 0; mt < 4; mt++) {
            uint32_t pa[2][4];
            #pragma unroll
            for (int nt = 0; nt < 4; nt++) {
                float p0 = mzero ? 0.f : __expf(S[mt][nt][0] - 2.0f);
                float p1 = mzero ? 0.f : __expf(S[mt][nt][1] - 2.0f);
                float p2 = mzero ? 0.f : __expf(S[mt][nt][2] - 2.0f);
                float p3 = mzero ? 0.f : __expf(S[mt][nt][3] - 2.0f);
                lsl[mt] += p0 + p1;
                lsh[mt] += p2 + p3;
                pa[nt >> 1][(nt & 1) * 2 + 0] = packh2(p0, p1);
                pa[nt >> 1][(nt & 1) * 2 + 1] = packh2(p2, p3);
            }
            #pragma unroll
            for (int ntd = 0; ntd < 4; ntd++)
                #pragma unroll
                for (int kv = 0; kv < 2; kv++)
                    mma16816(O[mt][ntd], pa[kv], vb[kv][ntd]);
        }
    }

    // ---- reduce row sums across the quad (n-direction) ----
    #pragma unroll
    for (int mt = 0; mt < 4; mt++) {
        lsl[mt] += __shfl_xor_sync(0xffffffffu, lsl[mt], 1);
        lsl[mt] += __shfl_xor_sync(0xffffffffu, lsl[mt], 2);
        lsh[mt] += __shfl_xor_sync(0xffffffffu, lsh[mt], 1);
        lsh[mt] += __shfl_xor_sync(0xffffffffu, lsh[mt], 2);
    }

    // ---- epilogue: O/lsum + lepe -> split fp16 hi/lo ----
    #pragma unroll
    for (int mt = 0; mt < 4; mt++) {
        float il = 1.f / lsl[mt], ih = 1.f / lsh[mt];
        int r0 = m0 + mt * 16 + g;
        #pragma unroll
        for (int ntd = 0; ntd < 4; ntd++) {
            size_t a0 = ((size_t)w * WIN + r0) * DIMC + n * HD + ntd * 8 + t2;
            size_t a1 = a0 + 8 * DIMC;
            float2 e0 = *(const float2*)(g_lepe + a0);
            float2 e1 = *(const float2*)(g_lepe + a1);
            float x0 = O[mt][ntd][0] * il + e0.x;
            float x1 = O[mt][ntd][1] * il + e0.y;
            float x2 = O[mt][ntd][2] * ih + e1.x;
            float x3 = O[mt][ntd][3] * ih + e1.y;
            split_store2(g_xhi + a0, g_xlo + a0, x0, x1);
            split_store2(g_xhi + a1, g_xlo + a1, x2, x3);
        }
    }
}

// ---------------------------------------------------------------------------
// Projection: out = x @ W^T + b, HMMA, A = x (hi/lo split), B = W fp16.
// Block 128(m) x 128(n), 8 warps (2m x 4n), K chunks of 32.
// ---------------------------------------------------------------------------
__global__ __launch_bounds__(256, 1) void proj_hmma(const float* __restrict__ W,
                                                    const float* __restrict__ bias,
                                                    float* __restrict__ out) {
    __shared__ __half Ah[128 * 40];
    __shared__ __half Al[128 * 40];
    __shared__ __half Bh[128 * 40];
    const int tid = threadIdx.x;
    const int m0 = blockIdx.y * 128, n0 = blockIdx.x * 128;
    const int wid = tid >> 5, lane = tid & 31;
    const int g = lane >> 2, t2 = (lane & 3) * 2;
    const int wm = (wid >> 2) * 64, wn = (wid & 3) * 32;

    float D[4][4][4];
    #pragma unroll
    for (int mt = 0; mt < 4; mt++)
        #pragma unroll
        for (int nt = 0; nt < 4; nt++)
            #pragma unroll
            for (int e = 0; e < 4; e++) D[mt][nt][e] = 0.f;

    for (int k0 = 0; k0 < DIMC; k0 += 32) {
        __syncthreads();
        #pragma unroll
        for (int jj = 0; jj < 8; jj++) {
            int i = tid + jj * 256;              // 0..2047 half2 units
            int row = i >> 4, hc = (i & 15) * 2;
            size_t gidx = (size_t)(m0 + row) * DIMC + k0 + hc;
            *(uint32_t*)&Ah[row * 40 + hc] = *(const uint32_t*)&g_xhi[gidx];
            *(uint32_t*)&Al[row * 40 + hc] = *(const uint32_t*)&g_xlo[gidx];
        }
        #pragma unroll
        for (int jj = 0; jj < 4; jj++) {
            int i = tid + jj * 256;              // 0..1023 float4 units
            int row = i >> 3, f4 = (i & 7) * 4;
            float4 wv = *(const float4*)&W[(size_t)(n0 + row) * DIMC + k0 + f4];
            *(__half2*)&Bh[row * 40 + f4]     = __floats2half2_rn(wv.x, wv.y);
            *(__half2*)&Bh[row * 40 + f4 + 2] = __floats2half2_rn(wv.z, wv.w);
        }
        __syncthreads();

        uint32_t bb[4][2][2];
        #pragma unroll
        for (int nt = 0; nt < 4; nt++)
            #pragma unroll
            for (int ks = 0; ks < 2; ks++) {
                const __half* p0 = &Bh[(wn + nt * 8 + g) * 40 + ks * 16 + t2];
                bb[nt][ks][0] = ldu32(p0);
                bb[nt][ks][1] = ldu32(p0 + 8);
            }
        #pragma unroll
        for (int pass = 0; pass < 2; pass++) {
            const __half* Ab = pass ? Al : Ah;
            uint32_t a[4][2][4];
            #pragma unroll
            for (int mt = 0; mt < 4; mt++)
                #pragma unroll
                for (int ks = 0; ks < 2; ks++) {
                    const __half* p0 = Ab + (wm + mt * 16 + g) * 40 + ks * 16 + t2;
                    a[mt][ks][0] = ldu32(p0);
                    a[mt][ks][1] = ldu32(p0 + 8 * 40);
                    a[mt][ks][2] = ldu32(p0 + 8);
                    a[mt][ks][3] = ldu32(p0 + 8 * 40 + 8);
                }
            #pragma unroll
            for (int mt = 0; mt < 4; mt++)
                #pragma unroll
                for (int nt = 0; nt < 4; nt++)
                    #pragma unroll
                    for (int ks = 0; ks < 2; ks++)
                        mma16816(D[mt][nt], a[mt][ks], bb[nt][ks]);
        }
    }

    // ---- scatter epilogue with bias ----
    #pragma unroll
    for (int mt = 0; mt < 4; mt++) {
        #pragma unroll
        for (int nt = 0; nt < 4; nt++) {
            int col = n0 + wn + nt * 8 + t2;
            float2 bv = *(const float2*)&bias[col];
            #pragma unroll
            for (int half = 0; half < 2; half++) {
                int mrow = m0 + wm + mt * 16 + g + half * 8;
                int wI = mrow >> 9, t = mrow & 511;
                int bI = wI >> 3, jI = wI & 7;
                int rI = t >> 3, c2I = t & 7;
                size_t o = ((size_t)bI * LTOK + rI * RESO + jI * 8 + c2I) * DIMC + col;
                float2 r;
                r.x = D[mt][nt][half * 2 + 0] + bv.x;
                r.y = D[mt][nt][half * 2 + 1] + bv.y;
                *(float2*)&out[o] = r;
            }
        }
    }
}

// ---------------------------------------------------------------------------
extern "C" void kernel_launch(void* const* d_in, const int* in_sizes, int n_in,
                              void* d_out, int out_size) {
    (void)in_sizes; (void)n_in; (void)out_size;
    const float* qkv    = (const float*)d_in[0];
    const float* scale  = (const float*)d_in[1];
    const float* proj_w = (const float*)d_in[2];
    const float* proj_b = (const float*)d_in[3];
    const float* conv_w = (const float*)d_in[4];
    const float* conv_b = (const float*)d_in[5];
    float* out = (float*)d_out;

    const float* v = qkv + 2ULL * BATCH * LTOK * DIMC;

    lepe_kernel<<<dim3(WIN, NWTOT), 256>>>(v, conv_w, conv_b);

    cudaFuncSetAttribute(attn_hmma, cudaFuncAttributeMaxDynamicSharedMemorySize,
                         ATTN_SMEM_BYTES);
    attn_hmma<<<dim3(NWTOT, NH), 256, ATTN_SMEM_BYTES>>>(qkv, scale);

    proj_hmma<<<dim3(DIMC / 128, (NWTOT * WIN) / 128), 256>>>(proj_w, proj_b, out);
}

// round 5
// speedup vs baseline: 5.2228x; 1.3324x over previous
#include <cuda_runtime.h>
#include <cuda_fp16.h>
#include <cstdint>

#define BATCH 8
#define RESO 64
#define DIMC 256
#define NH 8
#define HD 32
#define WIN 512
#define NWTOT 64
#define LTOK 4096

// ---------------------------------------------------------------------------
// Scratch (__device__ globals: allocation-free rule)
// ---------------------------------------------------------------------------
__device__ float  g_lepe[(size_t)NWTOT * WIN * DIMC];
__device__ __half g_xhi[(size_t)NWTOT * WIN * DIMC];
__device__ __half g_xlo[(size_t)NWTOT * WIN * DIMC];

// ---------------------------------------------------------------------------
// Helpers
// ---------------------------------------------------------------------------
__device__ __forceinline__ uint32_t ldu32(const __half* p) {
    return *reinterpret_cast<const uint32_t*>(p);
}
__device__ __forceinline__ uint32_t packh2(float x, float y) {
    __half2 h = __floats2half2_rn(x, y);
    return *reinterpret_cast<uint32_t*>(&h);
}
__device__ __forceinline__ void mma16816(float d[4], const uint32_t a[4],
                                         const uint32_t b[2]) {
    asm volatile(
        "mma.sync.aligned.m16n8k16.row.col.f32.f16.f16.f32 "
        "{%0,%1,%2,%3}, {%4,%5,%6,%7}, {%8,%9}, {%0,%1,%2,%3};\n"
        : "+f"(d[0]), "+f"(d[1]), "+f"(d[2]), "+f"(d[3])
        : "r"(a[0]), "r"(a[1]), "r"(a[2]), "r"(a[3]), "r"(b[0]), "r"(b[1]));
}
__device__ __forceinline__ void split_store4(__half* hi, __half* lo, float4 f) {
    __half h0 = __float2half_rn(f.x), h1 = __float2half_rn(f.y);
    __half h2 = __float2half_rn(f.z), h3 = __float2half_rn(f.w);
    *(__half2*)hi       = __halves2half2(h0, h1);
    *(__half2*)(hi + 2) = __halves2half2(h2, h3);
    *(__half2*)lo = __halves2half2(__float2half_rn(f.x - __half2float(h0)),
                                   __float2half_rn(f.y - __half2float(h1)));
    *(__half2*)(lo + 2) = __halves2half2(__float2half_rn(f.z - __half2float(h2)),
                                         __float2half_rn(f.w - __half2float(h3)));
}
__device__ __forceinline__ void split_store2(__half* hi, __half* lo, float x0, float x1) {
    __half h0 = __float2half_rn(x0), h1 = __float2half_rn(x1);
    *(__half2*)hi = __halves2half2(h0, h1);
    *(__half2*)lo = __halves2half2(__float2half_rn(x0 - __half2float(h0)),
                                   __float2half_rn(x1 - __half2float(h1)));
}

// ---------------------------------------------------------------------------
// LePE: depthwise 3x3 conv on V windows. Rolling 3-row register window.
// block = (slab of 8 rows, window), thread = channel. Each V elem loaded once.
// ---------------------------------------------------------------------------
__global__ __launch_bounds__(256) void lepe_kernel(const float* __restrict__ v,
                                                   const float* __restrict__ cw,
                                                   const float* __restrict__ cb) {
    const int slab = blockIdx.x;   // 0..7
    const int w = blockIdx.y;      // 0..63
    const int c = threadIdx.x;     // channel
    const int b = w >> 3, j = w & 7;
    float wt[9];
    #pragma unroll
    for (int i = 0; i < 9; i++) wt[i] = cw[c * 9 + i];
    const float bias = cb[c];
    const int r0 = slab * 8;
    const float* base = v + ((size_t)b * LTOK + j * 8) * DIMC + c;
    float* outb = g_lepe + (size_t)w * WIN * DIMC + c;

    float rows[3][8];
    #pragma unroll
    for (int cc = 0; cc < 8; cc++) {
        rows[0][cc] = (r0 == 0) ? 0.f : base[((size_t)(r0 - 1) * RESO + cc) * DIMC];
        rows[1][cc] = base[((size_t)r0 * RESO + cc) * DIMC];
    }
    #pragma unroll
    for (int rr = 0; rr < 8; rr++) {
        const int prv = rr % 3, cur = (rr + 1) % 3, nxt = (rr + 2) % 3;
        const int rn = r0 + rr + 1;
        #pragma unroll
        for (int cc = 0; cc < 8; cc++)
            rows[nxt][cc] = (rn >= RESO) ? 0.f : base[((size_t)rn * RESO + cc) * DIMC];
        const int rabs = r0 + rr;
        #pragma unroll
        for (int cc = 0; cc < 8; cc++) {
            float acc = bias;
            if (cc > 0) {
                acc += rows[prv][cc - 1] * wt[0];
                acc += rows[cur][cc - 1] * wt[3];
                acc += rows[nxt][cc - 1] * wt[6];
            }
            acc += rows[prv][cc] * wt[1];
            acc += rows[cur][cc] * wt[4];
            acc += rows[nxt][cc] * wt[7];
            if (cc < 7) {
                acc += rows[prv][cc + 1] * wt[2];
                acc += rows[cur][cc + 1] * wt[5];
                acc += rows[nxt][cc + 1] * wt[8];
            }
            outb[(size_t)(rabs * 8 + cc) * DIMC] = acc;
        }
    }
}

// ---------------------------------------------------------------------------
// HMMA flash attention. CTA = (window, head). 16 warps x 32 query rows.
// Q fragments persistent in registers (direct global load, hi/lo split).
// smem: Khi/Klo [512][40], Vt [32][520]  = 112.5 KB
// ---------------------------------------------------------------------------
#define KHIo 0
#define KLOo (512 * 40)
#define VTOo (2 * 512 * 40)
#define ATTN_SMEM_BYTES ((2 * 512 * 40 + 32 * 520) * 2)

__global__ __launch_bounds__(512, 1) void attn_hmma(const float* __restrict__ qkv,
                                                    const float* __restrict__ scale_p) {
    extern __shared__ __half sm[];
    const int tid = threadIdx.x;
    const int w = blockIdx.x, n = blockIdx.y;
    const int b = w >> 3, j = w & 7;
    const float qscale = scale_p[0] * 1.44269504f;   // fold log2(e)
    const float* qp = qkv;
    const float* kp = qkv + (size_t)BATCH * LTOK * DIMC;
    const float* vp = kp + (size_t)BATCH * LTOK * DIMC;

    // ---- fill K (hi+lo split) ----
    for (int i = tid; i < 512 * 8; i += 512) {
        int s = i >> 3, f4 = i & 7;
        int rs = s >> 3, cs = s & 7;
        size_t gbase = ((size_t)b * LTOK + rs * RESO + j * 8 + cs) * DIMC + n * HD + f4 * 4;
        float4 kf = *(const float4*)(kp + gbase);
        int so = s * 40 + f4 * 4;
        split_store4(sm + KHIo + so, sm + KLOo + so, kf);
    }
    // ---- fill Vt [d][key] ----
    for (int i = tid; i < 512 * 16; i += 512) {
        int key = i >> 4, dp = i & 15;
        int rs = key >> 3, cs = key & 7;
        const float* src = vp + ((size_t)b * LTOK + rs * RESO + j * 8 + cs) * DIMC + n * HD + dp * 2;
        float2 f = *(const float2*)src;
        sm[VTOo + (dp * 2) * 520 + key]     = __float2half_rn(f.x);
        sm[VTOo + (dp * 2 + 1) * 520 + key] = __float2half_rn(f.y);
    }

    const int wid = tid >> 5, lane = tid & 31;
    const int g = lane >> 2, t2 = (lane & 3) * 2;
    const int m0 = wid * 32;
    const bool mzero = (j == 7) && ((g < 4) != ((lane & 3) < 2));

    // ---- persistent Q fragments (direct global, scaled, hi/lo split) ----
    uint32_t qh[2][2][4], qlo[2][2][4];
    #pragma unroll
    for (int mt = 0; mt < 2; mt++) {
        #pragma unroll
        for (int rh = 0; rh < 2; rh++) {
            int row = m0 + mt * 16 + g + rh * 8;
            int rs = row >> 3, cs = row & 7;
            const float* src = qp + ((size_t)b * LTOK + rs * RESO + j * 8 + cs) * DIMC + n * HD;
            #pragma unroll
            for (int ks = 0; ks < 2; ks++) {
                #pragma unroll
                for (int ch = 0; ch < 2; ch++) {
                    float2 f = *(const float2*)(src + ks * 16 + ch * 8 + t2);
                    f.x *= qscale; f.y *= qscale;
                    __half h0 = __float2half_rn(f.x), h1 = __float2half_rn(f.y);
                    int e = rh + ch * 2;
                    __half2 hh = __halves2half2(h0, h1);
                    qh[mt][ks][e] = *reinterpret_cast<uint32_t*>(&hh);
                    qlo[mt][ks][e] = packh2(f.x - __half2float(h0),
                                            f.y - __half2float(h1));
                }
            }
        }
    }
    __syncthreads();

    float O[2][4][4];
    float lsl[2] = {0.f, 0.f}, lsh[2] = {0.f, 0.f};
    #pragma unroll
    for (int mt = 0; mt < 2; mt++)
        #pragma unroll
        for (int nt = 0; nt < 4; nt++)
            #pragma unroll
            for (int e = 0; e < 4; e++) O[mt][nt][e] = 0.f;

    for (int c = 0; c < 16; c++) {
        #pragma unroll
        for (int kh = 0; kh < 2; kh++) {
            const int kk = c * 32 + kh * 16;
            float S[2][2][4];
            #pragma unroll
            for (int mt = 0; mt < 2; mt++)
                #pragma unroll
                for (int nt = 0; nt < 2; nt++)
                    #pragma unroll
                    for (int e = 0; e < 4; e++) S[mt][nt][e] = 0.f;

            uint32_t bb[2][2][2];
            // K_hi fragments
            #pragma unroll
            for (int nt = 0; nt < 2; nt++)
                #pragma unroll
                for (int ks = 0; ks < 2; ks++) {
                    const __half* p0 = sm + KHIo + (kk + nt * 8 + g) * 40 + ks * 16 + t2;
                    bb[nt][ks][0] = ldu32(p0);
                    bb[nt][ks][1] = ldu32(p0 + 8);
                }
            #pragma unroll
            for (int mt = 0; mt < 2; mt++)
                #pragma unroll
                for (int nt = 0; nt < 2; nt++)
                    #pragma unroll
                    for (int ks = 0; ks < 2; ks++) {
                        mma16816(S[mt][nt], qh[mt][ks], bb[nt][ks]);
                        mma16816(S[mt][nt], qlo[mt][ks], bb[nt][ks]);
                    }
            // K_lo fragments (reuse bb regs)
            #pragma unroll
            for (int nt = 0; nt < 2; nt++)
                #pragma unroll
                for (int ks = 0; ks < 2; ks++) {
                    const __half* p0 = sm + KLOo + (kk + nt * 8 + g) * 40 + ks * 16 + t2;
                    bb[nt][ks][0] = ldu32(p0);
                    bb[nt][ks][1] = ldu32(p0 + 8);
                }
            #pragma unroll
            for (int mt = 0; mt < 2; mt++)
                #pragma unroll
                for (int nt = 0; nt < 2; nt++)
                    #pragma unroll
                    for (int ks = 0; ks < 2; ks++)
                        mma16816(S[mt][nt], qh[mt][ks], bb[nt][ks]);

            // ---- softmax exp (exp2, log2e pre-folded) + pack P ----
            uint32_t pa[2][4];
            #pragma unroll
            for (int mt = 0; mt < 2; mt++) {
                #pragma unroll
                for (int nt = 0; nt < 2; nt++) {
                    float p0 = mzero ? 0.f : exp2f(S[mt][nt][0]);
                    float p1 = mzero ? 0.f : exp2f(S[mt][nt][1]);
                    float p2 = mzero ? 0.f : exp2f(S[mt][nt][2]);
                    float p3 = mzero ? 0.f : exp2f(S[mt][nt][3]);
                    lsl[mt] += p0 + p1;
                    lsh[mt] += p2 + p3;
                    pa[mt][nt * 2 + 0] = packh2(p0, p1);
                    pa[mt][nt * 2 + 1] = packh2(p2, p3);
                }
            }
            // ---- PV for this 16-key slice ----
            uint32_t vb[4][2];
            #pragma unroll
            for (int ntd = 0; ntd < 4; ntd++) {
                const __half* p0 = sm + VTOo + (ntd * 8 + g) * 520 + kk + t2;
                vb[ntd][0] = ldu32(p0);
                vb[ntd][1] = ldu32(p0 + 8);
            }
            #pragma unroll
            for (int mt = 0; mt < 2; mt++)
                #pragma unroll
                for (int ntd = 0; ntd < 4; ntd++)
                    mma16816(O[mt][ntd], pa[mt], vb[ntd]);
        }
    }

    // ---- reduce row sums across the quad ----
    #pragma unroll
    for (int mt = 0; mt < 2; mt++) {
        lsl[mt] += __shfl_xor_sync(0xffffffffu, lsl[mt], 1);
        lsl[mt] += __shfl_xor_sync(0xffffffffu, lsl[mt], 2);
        lsh[mt] += __shfl_xor_sync(0xffffffffu, lsh[mt], 1);
        lsh[mt] += __shfl_xor_sync(0xffffffffu, lsh[mt], 2);
    }

    // ---- epilogue: O/lsum + lepe -> split fp16 hi/lo ----
    #pragma unroll
    for (int mt = 0; mt < 2; mt++) {
        float il = 1.f / lsl[mt], ih = 1.f / lsh[mt];
        int r0q = m0 + mt * 16 + g;
        #pragma unroll
        for (int ntd = 0; ntd < 4; ntd++) {
            size_t a0 = ((size_t)w * WIN + r0q) * DIMC + n * HD + ntd * 8 + t2;
            size_t a1 = a0 + 8 * DIMC;
            float2 e0 = *(const float2*)(g_lepe + a0);
            float2 e1 = *(const float2*)(g_lepe + a1);
            float x0 = O[mt][ntd][0] * il + e0.x;
            float x1 = O[mt][ntd][1] * il + e0.y;
            float x2 = O[mt][ntd][2] * ih + e1.x;
            float x3 = O[mt][ntd][3] * ih + e1.y;
            split_store2(g_xhi + a0, g_xlo + a0, x0, x1);
            split_store2(g_xhi + a1, g_xlo + a1, x2, x3);
        }
    }
}

// ---------------------------------------------------------------------------
// Projection: out = x @ W^T + b, HMMA, A = x (hi/lo split), B = W fp16.
// ---------------------------------------------------------------------------
__global__ __launch_bounds__(256, 1) void proj_hmma(const float* __restrict__ W,
                                                    const float* __restrict__ bias,
                                                    float* __restrict__ out) {
    __shared__ __half Ah[128 * 40];
    __shared__ __half Al[128 * 40];
    __shared__ __half Bh[128 * 40];
    const int tid = threadIdx.x;
    const int m0 = blockIdx.y * 128, n0 = blockIdx.x * 128;
    const int wid = tid >> 5, lane = tid & 31;
    const int g = lane >> 2, t2 = (lane & 3) * 2;
    const int wm = (wid >> 2) * 64, wn = (wid & 3) * 32;

    float D[4][4][4];
    #pragma unroll
    for (int mt = 0; mt < 4; mt++)
        #pragma unroll
        for (int nt = 0; nt < 4; nt++)
            #pragma unroll
            for (int e = 0; e < 4; e++) D[mt][nt][e] = 0.f;

    for (int k0 = 0; k0 < DIMC; k0 += 32) {
        __syncthreads();
        #pragma unroll
        for (int jj = 0; jj < 8; jj++) {
            int i = tid + jj * 256;
            int row = i >> 4, hc = (i & 15) * 2;
            size_t gidx = (size_t)(m0 + row) * DIMC + k0 + hc;
            *(uint32_t*)&Ah[row * 40 + hc] = *(const uint32_t*)&g_xhi[gidx];
            *(uint32_t*)&Al[row * 40 + hc] = *(const uint32_t*)&g_xlo[gidx];
        }
        #pragma unroll
        for (int jj = 0; jj < 4; jj++) {
            int i = tid + jj * 256;
            int row = i >> 3, f4 = (i & 7) * 4;
            float4 wv = *(const float4*)&W[(size_t)(n0 + row) * DIMC + k0 + f4];
            *(__half2*)&Bh[row * 40 + f4]     = __floats2half2_rn(wv.x, wv.y);
            *(__half2*)&Bh[row * 40 + f4 + 2] = __floats2half2_rn(wv.z, wv.w);
        }
        __syncthreads();

        uint32_t bb[4][2][2];
        #pragma unroll
        for (int nt = 0; nt < 4; nt++)
            #pragma unroll
            for (int ks = 0; ks < 2; ks++) {
                const __half* p0 = &Bh[(wn + nt * 8 + g) * 40 + ks * 16 + t2];
                bb[nt][ks][0] = ldu32(p0);
                bb[nt][ks][1] = ldu32(p0 + 8);
            }
        #pragma unroll
        for (int pass = 0; pass < 2; pass++) {
            const __half* Ab = pass ? Al : Ah;
            uint32_t a[4][2][4];
            #pragma unroll
            for (int mt = 0; mt < 4; mt++)
                #pragma unroll
                for (int ks = 0; ks < 2; ks++) {
                    const __half* p0 = Ab + (wm + mt * 16 + g) * 40 + ks * 16 + t2;
                    a[mt][ks][0] = ldu32(p0);
                    a[mt][ks][1] = ldu32(p0 + 8 * 40);
                    a[mt][ks][2] = ldu32(p0 + 8);
                    a[mt][ks][3] = ldu32(p0 + 8 * 40 + 8);
                }
            #pragma unroll
            for (int mt = 0; mt < 4; mt++)
                #pragma unroll
                for (int nt = 0; nt < 4; nt++)
                    #pragma unroll
                    for (int ks = 0; ks < 2; ks++)
                        mma16816(D[mt][nt], a[mt][ks], bb[nt][ks]);
        }
    }

    #pragma unroll
    for (int mt = 0; mt < 4; mt++) {
        #pragma unroll
        for (int nt = 0; nt < 4; nt++) {
            int col = n0 + wn + nt * 8 + t2;
            float2 bv = *(const float2*)&bias[col];
            #pragma unroll
            for (int half = 0; half < 2; half++) {
                int mrow = m0 + wm + mt * 16 + g + half * 8;
                int wI = mrow >> 9, t = mrow & 511;
                int bI = wI >> 3, jI = wI & 7;
                int rI = t >> 3, c2I = t & 7;
                size_t o = ((size_t)bI * LTOK + rI * RESO + jI * 8 + c2I) * DIMC + col;
                float2 r;
                r.x = D[mt][nt][half * 2 + 0] + bv.x;
                r.y = D[mt][nt][half * 2 + 1] + bv.y;
                *(float2*)&out[o] = r;
            }
        }
    }
}

// ---------------------------------------------------------------------------
extern "C" void kernel_launch(void* const* d_in, const int* in_sizes, int n_in,
                              void* d_out, int out_size) {
    (void)in_sizes; (void)n_in; (void)out_size;
    const float* qkv    = (const float*)d_in[0];
    const float* scale  = (const float*)d_in[1];
    const float* proj_w = (const float*)d_in[2];
    const float* proj_b = (const float*)d_in[3];
    const float* conv_w = (const float*)d_in[4];
    const float* conv_b = (const float*)d_in[5];
    float* out = (float*)d_out;

    const float* v = qkv + 2ULL * BATCH * LTOK * DIMC;

    lepe_kernel<<<dim3(8, NWTOT), 256>>>(v, conv_w, conv_b);

    cudaFuncSetAttribute(attn_hmma, cudaFuncAttributeMaxDynamicSharedMemorySize,
                         ATTN_SMEM_BYTES);
    attn_hmma<<<dim3(NWTOT, NH), 512, ATTN_SMEM_BYTES>>>(qkv, scale);

    proj_hmma<<<dim3(DIMC / 128, (NWTOT * WIN) / 128), 256>>>(proj_w, proj_b, out);
}

// round 6
// speedup vs baseline: 6.7133x; 1.2854x over previous
#include <cuda_runtime.h>
#include <cuda_fp16.h>
#include <cstdint>

#define BATCH 8
#define RESO 64
#define DIMC 256
#define NH 8
#define HD 32
#define WIN 512
#define NWTOT 64
#define LTOK 4096

// ---------------------------------------------------------------------------
// Scratch (__device__ globals: allocation-free rule)
// ---------------------------------------------------------------------------
__device__ float  g_lepe[(size_t)NWTOT * WIN * DIMC];
__device__ __half g_xhi[(size_t)NWTOT * WIN * DIMC];

// ---------------------------------------------------------------------------
// Helpers
// ---------------------------------------------------------------------------
__device__ __forceinline__ uint32_t ldu32(const __half* p) {
    return *reinterpret_cast<const uint32_t*>(p);
}
__device__ __forceinline__ uint32_t packh2(float x, float y) {
    __half2 h = __floats2half2_rn(x, y);
    return *reinterpret_cast<uint32_t*>(&h);
}
__device__ __forceinline__ void mma16816(float d[4], const uint32_t a[4],
                                         const uint32_t b[2]) {
    asm volatile(
        "mma.sync.aligned.m16n8k16.row.col.f32.f16.f16.f32 "
        "{%0,%1,%2,%3}, {%4,%5,%6,%7}, {%8,%9}, {%0,%1,%2,%3};\n"
        : "+f"(d[0]), "+f"(d[1]), "+f"(d[2]), "+f"(d[3])
        : "r"(a[0]), "r"(a[1]), "r"(a[2]), "r"(a[3]), "r"(b[0]), "r"(b[1]));
}

// ---------------------------------------------------------------------------
// LePE: depthwise 3x3 conv on V windows. Rolling 3-row register window.
// block = (slab of 4 rows, window), thread = channel.
// ---------------------------------------------------------------------------
__global__ __launch_bounds__(256) void lepe_kernel(const float* __restrict__ v,
                                                   const float* __restrict__ cw,
                                                   const float* __restrict__ cb) {
    const int slab = blockIdx.x;   // 0..15
    const int w = blockIdx.y;      // 0..63
    const int c = threadIdx.x;     // channel
    const int b = w >> 3, j = w & 7;
    float wt[9];
    #pragma unroll
    for (int i = 0; i < 9; i++) wt[i] = cw[c * 9 + i];
    const float bias = cb[c];
    const int r0 = slab * 4;
    const float* base = v + ((size_t)b * LTOK + j * 8) * DIMC + c;
    float* outb = g_lepe + (size_t)w * WIN * DIMC + c;

    float rows[3][8];
    #pragma unroll
    for (int cc = 0; cc < 8; cc++) {
        rows[0][cc] = (r0 == 0) ? 0.f : base[((size_t)(r0 - 1) * RESO + cc) * DIMC];
        rows[1][cc] = base[((size_t)r0 * RESO + cc) * DIMC];
    }
    #pragma unroll
    for (int rr = 0; rr < 4; rr++) {
        const int prv = rr % 3, cur = (rr + 1) % 3, nxt = (rr + 2) % 3;
        const int rn = r0 + rr + 1;
        #pragma unroll
        for (int cc = 0; cc < 8; cc++)
            rows[nxt][cc] = (rn >= RESO) ? 0.f : base[((size_t)rn * RESO + cc) * DIMC];
        const int rabs = r0 + rr;
        #pragma unroll
        for (int cc = 0; cc < 8; cc++) {
            float acc = bias;
            if (cc > 0) {
                acc += rows[prv][cc - 1] * wt[0];
                acc += rows[cur][cc - 1] * wt[3];
                acc += rows[nxt][cc - 1] * wt[6];
            }
            acc += rows[prv][cc] * wt[1];
            acc += rows[cur][cc] * wt[4];
            acc += rows[nxt][cc] * wt[7];
            if (cc < 7) {
                acc += rows[prv][cc + 1] * wt[2];
                acc += rows[cur][cc + 1] * wt[5];
                acc += rows[nxt][cc + 1] * wt[8];
            }
            outb[(size_t)(rabs * 8 + cc) * DIMC] = acc;
        }
    }
}

// ---------------------------------------------------------------------------
// HMMA flash attention. CTA = (window, head, quarter). 8 warps x 16 query rows.
// Q fragments persistent in registers (hi/lo split); K fp16 hi-only in smem.
// smem: Kh [512][40], Vt [32][520]  = 72.5 KB -> 3 CTAs/SM (24 warps)
// ---------------------------------------------------------------------------
#define KHIo 0
#define VTOo (512 * 40)
#define ATTN_SMEM_BYTES ((512 * 40 + 32 * 520) * 2)

__global__ __launch_bounds__(256, 3) void attn_hmma(const float* __restrict__ qkv,
                                                    const float* __restrict__ scale_p) {
    extern __shared__ __half sm[];
    const int tid = threadIdx.x;
    const int w = blockIdx.x, n = blockIdx.y, z = blockIdx.z;
    const int b = w >> 3, j = w & 7;
    const float qscale = scale_p[0] * 1.44269504f;   // fold log2(e)
    const float* qp = qkv;
    const float* kp = qkv + (size_t)BATCH * LTOK * DIMC;
    const float* vp = kp + (size_t)BATCH * LTOK * DIMC;

    // ---- fill K (fp16 hi only) ----
    for (int i = tid; i < 512 * 8; i += 256) {
        int s = i >> 3, f4 = i & 7;
        int rs = s >> 3, cs = s & 7;
        size_t gbase = ((size_t)b * LTOK + rs * RESO + j * 8 + cs) * DIMC + n * HD + f4 * 4;
        float4 kf = *(const float4*)(kp + gbase);
        int so = s * 40 + f4 * 4;
        *(__half2*)(sm + KHIo + so)     = __floats2half2_rn(kf.x, kf.y);
        *(__half2*)(sm + KHIo + so + 2) = __floats2half2_rn(kf.z, kf.w);
    }
    // ---- fill Vt [d][key] ----
    for (int i = tid; i < 512 * 16; i += 256) {
        int key = i >> 4, dp = i & 15;
        int rs = key >> 3, cs = key & 7;
        const float* src = vp + ((size_t)b * LTOK + rs * RESO + j * 8 + cs) * DIMC + n * HD + dp * 2;
        float2 f = *(const float2*)src;
        sm[VTOo + (dp * 2) * 520 + key]     = __float2half_rn(f.x);
        sm[VTOo + (dp * 2 + 1) * 520 + key] = __float2half_rn(f.y);
    }

    const int wid = tid >> 5, lane = tid & 31;
    const int g = lane >> 2, t2 = (lane & 3) * 2;
    const int m0 = z * 128 + wid * 16;
    const bool mzero = (j == 7) && ((g < 4) != ((lane & 3) < 2));

    // ---- persistent Q fragments (direct global, scaled, hi/lo split) ----
    uint32_t qh[2][4], ql[2][4];
    #pragma unroll
    for (int rh = 0; rh < 2; rh++) {
        int row = m0 + g + rh * 8;
        int rs = row >> 3, cs = row & 7;
        const float* src = qp + ((size_t)b * LTOK + rs * RESO + j * 8 + cs) * DIMC + n * HD;
        #pragma unroll
        for (int ks = 0; ks < 2; ks++) {
            #pragma unroll
            for (int ch = 0; ch < 2; ch++) {
                float2 f = *(const float2*)(src + ks * 16 + ch * 8 + t2);
                f.x *= qscale; f.y *= qscale;
                __half h0 = __float2half_rn(f.x), h1 = __float2half_rn(f.y);
                int e = rh + ch * 2;
                __half2 hh = __halves2half2(h0, h1);
                qh[ks][e] = *reinterpret_cast<uint32_t*>(&hh);
                ql[ks][e] = packh2(f.x - __half2float(h0), f.y - __half2float(h1));
            }
        }
    }
    __syncthreads();

    float O[4][4];
    float lsl = 0.f, lsh = 0.f;
    #pragma unroll
    for (int nt = 0; nt < 4; nt++)
        #pragma unroll
        for (int e = 0; e < 4; e++) O[nt][e] = 0.f;

    #pragma unroll 2
    for (int step = 0; step < 32; step++) {
        const int kk = step * 16;
        float S[2][4];
        #pragma unroll
        for (int nt = 0; nt < 2; nt++)
            #pragma unroll
            for (int e = 0; e < 4; e++) S[nt][e] = 0.f;

        uint32_t bb[2][2][2];
        #pragma unroll
        for (int nt = 0; nt < 2; nt++)
            #pragma unroll
            for (int ks = 0; ks < 2; ks++) {
                const __half* p0 = sm + KHIo + (kk + nt * 8 + g) * 40 + ks * 16 + t2;
                bb[nt][ks][0] = ldu32(p0);
                bb[nt][ks][1] = ldu32(p0 + 8);
            }
        #pragma unroll
        for (int nt = 0; nt < 2; nt++)
            #pragma unroll
            for (int ks = 0; ks < 2; ks++) {
                mma16816(S[nt], qh[ks], bb[nt][ks]);
                mma16816(S[nt], ql[ks], bb[nt][ks]);
            }

        // ---- softmax exp (exp2, log2e pre-folded) + pack P ----
        uint32_t pa[4];
        #pragma unroll
        for (int nt = 0; nt < 2; nt++) {
            float p0 = mzero ? 0.f : exp2f(S[nt][0]);
            float p1 = mzero ? 0.f : exp2f(S[nt][1]);
            float p2 = mzero ? 0.f : exp2f(S[nt][2]);
            float p3 = mzero ? 0.f : exp2f(S[nt][3]);
            lsl += p0 + p1;
            lsh += p2 + p3;
            pa[nt * 2 + 0] = packh2(p0, p1);
            pa[nt * 2 + 1] = packh2(p2, p3);
        }
        // ---- PV for this 16-key slice ----
        uint32_t vb[4][2];
        #pragma unroll
        for (int ntd = 0; ntd < 4; ntd++) {
            const __half* p0 = sm + VTOo + (ntd * 8 + g) * 520 + kk + t2;
            vb[ntd][0] = ldu32(p0);
            vb[ntd][1] = ldu32(p0 + 8);
        }
        #pragma unroll
        for (int ntd = 0; ntd < 4; ntd++)
            mma16816(O[ntd], pa, vb[ntd]);
    }

    // ---- reduce row sums across the quad ----
    lsl += __shfl_xor_sync(0xffffffffu, lsl, 1);
    lsl += __shfl_xor_sync(0xffffffffu, lsl, 2);
    lsh += __shfl_xor_sync(0xffffffffu, lsh, 1);
    lsh += __shfl_xor_sync(0xffffffffu, lsh, 2);

    // ---- epilogue: O/lsum + lepe -> fp16 ----
    const float il = 1.f / lsl, ih = 1.f / lsh;
    const int r0q = m0 + g;
    #pragma unroll
    for (int ntd = 0; ntd < 4; ntd++) {
        size_t a0 = ((size_t)w * WIN + r0q) * DIMC + n * HD + ntd * 8 + t2;
        size_t a1 = a0 + 8 * DIMC;
        float2 e0 = *(const float2*)(g_lepe + a0);
        float2 e1 = *(const float2*)(g_lepe + a1);
        *(__half2*)(g_xhi + a0) = __floats2half2_rn(O[ntd][0] * il + e0.x,
                                                    O[ntd][1] * il + e0.y);
        *(__half2*)(g_xhi + a1) = __floats2half2_rn(O[ntd][2] * ih + e1.x,
                                                    O[ntd][3] * ih + e1.y);
    }
}

// ---------------------------------------------------------------------------
// Projection: out = x @ W^T + b, HMMA, A = x fp16, B = W fp16 (single pass).
// ---------------------------------------------------------------------------
__global__ __launch_bounds__(256, 1) void proj_hmma(const float* __restrict__ W,
                                                    const float* __restrict__ bias,
                                                    float* __restrict__ out) {
    __shared__ __half Ah[128 * 40];
    __shared__ __half Bh[128 * 40];
    const int tid = threadIdx.x;
    const int m0 = blockIdx.y * 128, n0 = blockIdx.x * 128;
    const int wid = tid >> 5, lane = tid & 31;
    const int g = lane >> 2, t2 = (lane & 3) * 2;
    const int wm = (wid >> 2) * 64, wn = (wid & 3) * 32;

    float D[4][4][4];
    #pragma unroll
    for (int mt = 0; mt < 4; mt++)
        #pragma unroll
        for (int nt = 0; nt < 4; nt++)
            #pragma unroll
            for (int e = 0; e < 4; e++) D[mt][nt][e] = 0.f;

    for (int k0 = 0; k0 < DIMC; k0 += 32) {
        __syncthreads();
        #pragma unroll
        for (int jj = 0; jj < 8; jj++) {
            int i = tid + jj * 256;
            int row = i >> 4, hc = (i & 15) * 2;
            size_t gidx = (size_t)(m0 + row) * DIMC + k0 + hc;
            *(uint32_t*)&Ah[row * 40 + hc] = *(const uint32_t*)&g_xhi[gidx];
        }
        #pragma unroll
        for (int jj = 0; jj < 4; jj++) {
            int i = tid + jj * 256;
            int row = i >> 3, f4 = (i & 7) * 4;
            float4 wv = *(const float4*)&W[(size_t)(n0 + row) * DIMC + k0 + f4];
            *(__half2*)&Bh[row * 40 + f4]     = __floats2half2_rn(wv.x, wv.y);
            *(__half2*)&Bh[row * 40 + f4 + 2] = __floats2half2_rn(wv.z, wv.w);
        }
        __syncthreads();

        uint32_t bb[4][2][2];
        #pragma unroll
        for (int nt = 0; nt < 4; nt++)
            #pragma unroll
            for (int ks = 0; ks < 2; ks++) {
                const __half* p0 = &Bh[(wn + nt * 8 + g) * 40 + ks * 16 + t2];
                bb[nt][ks][0] = ldu32(p0);
                bb[nt][ks][1] = ldu32(p0 + 8);
            }
        uint32_t a[4][2][4];
        #pragma unroll
        for (int mt = 0; mt < 4; mt++)
            #pragma unroll
            for (int ks = 0; ks < 2; ks++) {
                const __half* p0 = Ah + (wm + mt * 16 + g) * 40 + ks * 16 + t2;
                a[mt][ks][0] = ldu32(p0);
                a[mt][ks][1] = ldu32(p0 + 8 * 40);
                a[mt][ks][2] = ldu32(p0 + 8);
                a[mt][ks][3] = ldu32(p0 + 8 * 40 + 8);
            }
        #pragma unroll
        for (int mt = 0; mt < 4; mt++)
            #pragma unroll
            for (int nt = 0; nt < 4; nt++)
                #pragma unroll
                for (int ks = 0; ks < 2; ks++)
                    mma16816(D[mt][nt], a[mt][ks], bb[nt][ks]);
    }

    #pragma unroll
    for (int mt = 0; mt < 4; mt++) {
        #pragma unroll
        for (int nt = 0; nt < 4; nt++) {
            int col = n0 + wn + nt * 8 + t2;
            float2 bv = *(const float2*)&bias[col];
            #pragma unroll
            for (int half = 0; half < 2; half++) {
                int mrow = m0 + wm + mt * 16 + g + half * 8;
                int wI = mrow >> 9, t = mrow & 511;
                int bI = wI >> 3, jI = wI & 7;
                int rI = t >> 3, c2I = t & 7;
                size_t o = ((size_t)bI * LTOK + rI * RESO + jI * 8 + c2I) * DIMC + col;
                float2 r;
                r.x = D[mt][nt][half * 2 + 0] + bv.x;
                r.y = D[mt][nt][half * 2 + 1] + bv.y;
                *(float2*)&out[o] = r;
            }
        }
    }
}

// ---------------------------------------------------------------------------
extern "C" void kernel_launch(void* const* d_in, const int* in_sizes, int n_in,
                              void* d_out, int out_size) {
    (void)in_sizes; (void)n_in; (void)out_size;
    const float* qkv    = (const float*)d_in[0];
    const float* scale  = (const float*)d_in[1];
    const float* proj_w = (const float*)d_in[2];
    const float* proj_b = (const float*)d_in[3];
    const float* conv_w = (const float*)d_in[4];
    const float* conv_b = (const float*)d_in[5];
    float* out = (float*)d_out;

    const float* v = qkv + 2ULL * BATCH * LTOK * DIMC;

    lepe_kernel<<<dim3(16, NWTOT), 256>>>(v, conv_w, conv_b);

    cudaFuncSetAttribute(attn_hmma, cudaFuncAttributeMaxDynamicSharedMemorySize,
                         ATTN_SMEM_BYTES);
    attn_hmma<<<dim3(NWTOT, NH, 4), 256, ATTN_SMEM_BYTES>>>(qkv, scale);

    proj_hmma<<<dim3(DIMC / 128, (NWTOT * WIN) / 128), 256>>>(proj_w, proj_b, out);
}

// round 7
// speedup vs baseline: 8.2946x; 1.2356x over previous
#include <cuda_runtime.h>
#include <cuda_fp16.h>
#include <cstdint>

#define BATCH 8
#define RESO 64
#define DIMC 256
#define NH 8
#define HD 32
#define WIN 512
#define NWTOT 64
#define LTOK 4096

// ---------------------------------------------------------------------------
// Scratch (__device__ globals: allocation-free rule)
// ---------------------------------------------------------------------------
__device__ __align__(16) float  g_lepe[(size_t)NWTOT * WIN * DIMC];
__device__ __align__(16) __half g_xhi[(size_t)NWTOT * WIN * DIMC];
__device__ __align__(16) __half g_kh[(size_t)NWTOT * NH * WIN * 40];   // [w][n][key][40]
__device__ __align__(16) __half g_vt[(size_t)NWTOT * NH * 32 * 520];   // [w][n][d][520]

// ---------------------------------------------------------------------------
// Helpers
// ---------------------------------------------------------------------------
__device__ __forceinline__ uint32_t ldu32(const __half* p) {
    return *reinterpret_cast<const uint32_t*>(p);
}
__device__ __forceinline__ uint32_t packh2(float x, float y) {
    __half2 h = __floats2half2_rn(x, y);
    return *reinterpret_cast<uint32_t*>(&h);
}
__device__ __forceinline__ uint32_t smem_u32(const void* p) {
    uint32_t a;
    asm("{ .reg .u64 t; cvta.to.shared.u64 t, %1; cvt.u32.u64 %0, t; }"
        : "=r"(a) : "l"(p));
    return a;
}
__device__ __forceinline__ void mma16816(float d[4], const uint32_t a[4],
                                         const uint32_t b[2]) {
    asm volatile(
        "mma.sync.aligned.m16n8k16.row.col.f32.f16.f16.f32 "
        "{%0,%1,%2,%3}, {%4,%5,%6,%7}, {%8,%9}, {%0,%1,%2,%3};\n"
        : "+f"(d[0]), "+f"(d[1]), "+f"(d[2]), "+f"(d[3])
        : "r"(a[0]), "r"(a[1]), "r"(a[2]), "r"(a[3]), "r"(b[0]), "r"(b[1]));
}
#define LDSM_X4(r0, r1, r2, r3, addr) \
    asm volatile("ldmatrix.sync.aligned.m8n8.x4.shared.b16 {%0,%1,%2,%3}, [%4];" \
                 : "=r"(r0), "=r"(r1), "=r"(r2), "=r"(r3) : "r"(addr))

// ---------------------------------------------------------------------------
// prep_k: K fp32 -> fp16 into padded smem-image layout [w][n][key][40]
// ---------------------------------------------------------------------------
__global__ __launch_bounds__(256) void prep_k(const float* __restrict__ qkv) {
    const float* kp = qkv + (size_t)BATCH * LTOK * DIMC;
    const int w = blockIdx.y, b = w >> 3, j = w & 7;
    const int tid = threadIdx.x;
    const int d = tid & 31, kloc = tid >> 5;
    const int key = blockIdx.x * 8 + kloc;
    const int rs = key >> 3, cs = key & 7;
    const float* src = kp + ((size_t)b * LTOK + rs * RESO + j * 8 + cs) * DIMC + d;
    __half* dst = g_kh + ((size_t)(w * NH) * WIN + key) * 40 + d;
    #pragma unroll
    for (int n = 0; n < NH; n++)
        dst[(size_t)n * WIN * 40] = __float2half_rn(src[n * 32]);
}

// ---------------------------------------------------------------------------
// LePE: depthwise 3x3 conv on V windows (rolling register window).
// Also emits Vt fp16 [w][n][d][520] (one aligned uint4 per row) for attention.
// ---------------------------------------------------------------------------
__global__ __launch_bounds__(256) void lepe_kernel(const float* __restrict__ v,
                                                   const float* __restrict__ cw,
                                                   const float* __restrict__ cb) {
    const int slab = blockIdx.x;   // 0..15
    const int w = blockIdx.y;      // 0..63
    const int c = threadIdx.x;     // channel
    const int b = w >> 3, j = w & 7;
    const int n = c >> 5, d = c & 31;
    float wt[9];
    #pragma unroll
    for (int i = 0; i < 9; i++) wt[i] = cw[c * 9 + i];
    const float bias = cb[c];
    const int r0 = slab * 4;
    const float* base = v + ((size_t)b * LTOK + j * 8) * DIMC + c;
    float* outb = g_lepe + (size_t)w * WIN * DIMC + c;
    __half* vtb = g_vt + ((size_t)(w * NH + n) * 32 + d) * 520;

    float rows[3][8];
    #pragma unroll
    for (int cc = 0; cc < 8; cc++) {
        rows[0][cc] = (r0 == 0) ? 0.f : base[((size_t)(r0 - 1) * RESO + cc) * DIMC];
        rows[1][cc] = base[((size_t)r0 * RESO + cc) * DIMC];
    }
    #pragma unroll
    for (int rr = 0; rr < 4; rr++) {
        const int prv = rr % 3, cur = (rr + 1) % 3, nxt = (rr + 2) % 3;
        const int rn = r0 + rr + 1;
        #pragma unroll
        for (int cc = 0; cc < 8; cc++)
            rows[nxt][cc] = (rn >= RESO) ? 0.f : base[((size_t)rn * RESO + cc) * DIMC];
        const int rabs = r0 + rr;
        // Vt emit: 8 halves of this row, one 16B store
        {
            union { uint4 u; __half h[8]; } pk;
            #pragma unroll
            for (int cc = 0; cc < 8; cc++) pk.h[cc] = __float2half_rn(rows[cur][cc]);
            *(uint4*)(vtb + rabs * 8) = pk.u;
        }
        #pragma unroll
        for (int cc = 0; cc < 8; cc++) {
            float acc = bias;
            if (cc > 0) {
                acc += rows[prv][cc - 1] * wt[0];
                acc += rows[cur][cc - 1] * wt[3];
                acc += rows[nxt][cc - 1] * wt[6];
            }
            acc += rows[prv][cc] * wt[1];
            acc += rows[cur][cc] * wt[4];
            acc += rows[nxt][cc] * wt[7];
            if (cc < 7) {
                acc += rows[prv][cc + 1] * wt[2];
                acc += rows[cur][cc + 1] * wt[5];
                acc += rows[nxt][cc + 1] * wt[8];
            }
            outb[(size_t)(rabs * 8 + cc) * DIMC] = acc;
        }
    }
}

// ---------------------------------------------------------------------------
// HMMA flash attention. CTA = (window, head, quarter). 8 warps x 16 query rows.
// Q fp16 persistent in registers; K fp16 [512][40] + Vt fp16 [32][520] in smem
// (filled by pure uint4 copies from g_kh/g_vt). ldmatrix fragment loads.
// smem = 72.5 KB -> 3 CTAs/SM.
// ---------------------------------------------------------------------------
#define VTOo (512 * 40)          // halves
#define VTOBYTES (512 * 40 * 2)  // 40960
#define ATTN_SMEM_BYTES ((512 * 40 + 32 * 520) * 2)

__global__ __launch_bounds__(256, 3) void attn_hmma(const float* __restrict__ qkv,
                                                    const float* __restrict__ scale_p) {
    extern __shared__ __half sm[];
    const int tid = threadIdx.x;
    const int w = blockIdx.x, n = blockIdx.y, z = blockIdx.z;
    const int b = w >> 3, j = w & 7;
    const float qscale = scale_p[0] * 1.44269504f;   // fold log2(e)

    // ---- fill K & Vt by aligned vector copy ----
    {
        const uint4* gk = (const uint4*)(g_kh + (size_t)(w * NH + n) * WIN * 40);
        uint4* dk = (uint4*)sm;
        #pragma unroll
        for (int i = 0; i < 10; i++) dk[tid + i * 256] = gk[tid + i * 256];
        const uint4* gv = (const uint4*)(g_vt + (size_t)(w * NH + n) * 32 * 520);
        uint4* dv = (uint4*)(sm + VTOo);
        #pragma unroll
        for (int i = 0; i < 8; i++) dv[tid + i * 256] = gv[tid + i * 256];
        if (tid < 2080 - 2048) dv[tid + 2048] = gv[tid + 2048];
    }

    const int wid = tid >> 5, lane = tid & 31;
    const int g = lane >> 2, t2 = (lane & 3) * 2;
    const int m0 = z * 128 + wid * 16;
    const bool mzero = (j == 7) && ((g < 4) != ((lane & 3) < 2));

    // ---- persistent Q fragments (direct global, scaled, fp16) ----
    uint32_t qh[2][4];
    #pragma unroll
    for (int rh = 0; rh < 2; rh++) {
        int row = m0 + g + rh * 8;
        int rs = row >> 3, cs = row & 7;
        const float* src = qkv + ((size_t)b * LTOK + rs * RESO + j * 8 + cs) * DIMC + n * HD;
        #pragma unroll
        for (int ks = 0; ks < 2; ks++) {
            #pragma unroll
            for (int ch = 0; ch < 2; ch++) {
                float2 f = *(const float2*)(src + ks * 16 + ch * 8 + t2);
                qh[ks][rh + ch * 2] = packh2(f.x * qscale, f.y * qscale);
            }
        }
    }
    __syncthreads();

    const uint32_t sb = smem_u32(sm);
    const uint32_t kconst = sb + (uint32_t)((lane & 7) * 80 + (lane >> 3) * 16);
    const uint32_t vconst = sb + VTOBYTES +
        (uint32_t)((((lane >> 4) * 8) + (lane & 7)) * 1040 + ((lane >> 3) & 1) * 16);

    float O[4][4];
    float lsl = 0.f, lsh = 0.f;
    #pragma unroll
    for (int nt = 0; nt < 4; nt++)
        #pragma unroll
        for (int e = 0; e < 4; e++) O[nt][e] = 0.f;

    #pragma unroll 4
    for (int step = 0; step < 32; step++) {
        float S[2][4];
        #pragma unroll
        for (int nt = 0; nt < 2; nt++)
            #pragma unroll
            for (int e = 0; e < 4; e++) S[nt][e] = 0.f;

        // K fragments: 2x ldmatrix.x4 (keys step*16+0..7 and +8..15)
        uint32_t kb[2][2][2];
        LDSM_X4(kb[0][0][0], kb[0][0][1], kb[0][1][0], kb[0][1][1],
                kconst + (uint32_t)step * 1280u);
        LDSM_X4(kb[1][0][0], kb[1][0][1], kb[1][1][0], kb[1][1][1],
                kconst + (uint32_t)step * 1280u + 640u);
        #pragma unroll
        for (int nt = 0; nt < 2; nt++)
            #pragma unroll
            for (int ks = 0; ks < 2; ks++)
                mma16816(S[nt], qh[ks], kb[nt][ks]);

        // ---- softmax exp (exp2, log2e pre-folded) + pack P ----
        uint32_t pa[4];
        #pragma unroll
        for (int nt = 0; nt < 2; nt++) {
            float p0 = mzero ? 0.f : exp2f(S[nt][0]);
            float p1 = mzero ? 0.f : exp2f(S[nt][1]);
            float p2 = mzero ? 0.f : exp2f(S[nt][2]);
            float p3 = mzero ? 0.f : exp2f(S[nt][3]);
            lsl += p0 + p1;
            lsh += p2 + p3;
            pa[nt * 2 + 0] = packh2(p0, p1);
            pa[nt * 2 + 1] = packh2(p2, p3);
        }

        // V fragments: 2x ldmatrix.x4 (d 0..15 and 16..31)
        uint32_t vb[4][2];
        LDSM_X4(vb[0][0], vb[0][1], vb[1][0], vb[1][1],
                vconst + (uint32_t)step * 32u);
        LDSM_X4(vb[2][0], vb[2][1], vb[3][0], vb[3][1],
                vconst + (uint32_t)step * 32u + 16640u);
        #pragma unroll
        for (int ntd = 0; ntd < 4; ntd++)
            mma16816(O[ntd], pa, vb[ntd]);
    }

    // ---- reduce row sums across the quad ----
    lsl += __shfl_xor_sync(0xffffffffu, lsl, 1);
    lsl += __shfl_xor_sync(0xffffffffu, lsl, 2);
    lsh += __shfl_xor_sync(0xffffffffu, lsh, 1);
    lsh += __shfl_xor_sync(0xffffffffu, lsh, 2);

    // ---- epilogue: O/lsum + lepe -> fp16 ----
    const float il = 1.f / lsl, ih = 1.f / lsh;
    const int r0q = m0 + g;
    #pragma unroll
    for (int ntd = 0; ntd < 4; ntd++) {
        size_t a0 = ((size_t)w * WIN + r0q) * DIMC + n * HD + ntd * 8 + t2;
        size_t a1 = a0 + 8 * DIMC;
        float2 e0 = *(const float2*)(g_lepe + a0);
        float2 e1 = *(const float2*)(g_lepe + a1);
        *(__half2*)(g_xhi + a0) = __floats2half2_rn(O[ntd][0] * il + e0.x,
                                                    O[ntd][1] * il + e0.y);
        *(__half2*)(g_xhi + a1) = __floats2half2_rn(O[ntd][2] * ih + e1.x,
                                                    O[ntd][3] * ih + e1.y);
    }
}

// ---------------------------------------------------------------------------
// Projection: out = x @ W^T + b, HMMA, A = x fp16, B = W fp16.
// ---------------------------------------------------------------------------
__global__ __launch_bounds__(256, 1) void proj_hmma(const float* __restrict__ W,
                                                    const float* __restrict__ bias,
                                                    float* __restrict__ out) {
    __shared__ __half Ah[128 * 40];
    __shared__ __half Bh[128 * 40];
    const int tid = threadIdx.x;
    const int m0 = blockIdx.y * 128, n0 = blockIdx.x * 128;
    const int wid = tid >> 5, lane = tid & 31;
    const int g = lane >> 2, t2 = (lane & 3) * 2;
    const int wm = (wid >> 2) * 64, wn = (wid & 3) * 32;

    float D[4][4][4];
    #pragma unroll
    for (int mt = 0; mt < 4; mt++)
        #pragma unroll
        for (int nt = 0; nt < 4; nt++)
            #pragma unroll
            for (int e = 0; e < 4; e++) D[mt][nt][e] = 0.f;

    for (int k0 = 0; k0 < DIMC; k0 += 32) {
        __syncthreads();
        #pragma unroll
        for (int jj = 0; jj < 8; jj++) {
            int i = tid + jj * 256;
            int row = i >> 4, hc = (i & 15) * 2;
            size_t gidx = (size_t)(m0 + row) * DIMC + k0 + hc;
            *(uint32_t*)&Ah[row * 40 + hc] = *(const uint32_t*)&g_xhi[gidx];
        }
        #pragma unroll
        for (int jj = 0; jj < 4; jj++) {
            int i = tid + jj * 256;
            int row = i >> 3, f4 = (i & 7) * 4;
            float4 wv = *(const float4*)&W[(size_t)(n0 + row) * DIMC + k0 + f4];
            *(__half2*)&Bh[row * 40 + f4]     = __floats2half2_rn(wv.x, wv.y);
            *(__half2*)&Bh[row * 40 + f4 + 2] = __floats2half2_rn(wv.z, wv.w);
        }
        __syncthreads();

        uint32_t bb[4][2][2];
        #pragma unroll
        for (int nt = 0; nt < 4; nt++)
            #pragma unroll
            for (int ks = 0; ks < 2; ks++) {
                const __half* p0 = &Bh[(wn + nt * 8 + g) * 40 + ks * 16 + t2];
                bb[nt][ks][0] = ldu32(p0);
                bb[nt][ks][1] = ldu32(p0 + 8);
            }
        uint32_t a[4][2][4];
        #pragma unroll
        for (int mt = 0; mt < 4; mt++)
            #pragma unroll
            for (int ks = 0; ks < 2; ks++) {
                const __half* p0 = Ah + (wm + mt * 16 + g) * 40 + ks * 16 + t2;
                a[mt][ks][0] = ldu32(p0);
                a[mt][ks][1] = ldu32(p0 + 8 * 40);
                a[mt][ks][2] = ldu32(p0 + 8);
                a[mt][ks][3] = ldu32(p0 + 8 * 40 + 8);
            }
        #pragma unroll
        for (int mt = 0; mt < 4; mt++)
            #pragma unroll
            for (int nt = 0; nt < 4; nt++)
                #pragma unroll
                for (int ks = 0; ks < 2; ks++)
                    mma16816(D[mt][nt], a[mt][ks], bb[nt][ks]);
    }

    #pragma unroll
    for (int mt = 0; mt < 4; mt++) {
        #pragma unroll
        for (int nt = 0; nt < 4; nt++) {
            int col = n0 + wn + nt * 8 + t2;
            float2 bv = *(const float2*)&bias[col];
            #pragma unroll
            for (int half = 0; half < 2; half++) {
                int mrow = m0 + wm + mt * 16 + g + half * 8;
                int wI = mrow >> 9, t = mrow & 511;
                int bI = wI >> 3, jI = wI & 7;
                int rI = t >> 3, c2I = t & 7;
                size_t o = ((size_t)bI * LTOK + rI * RESO + jI * 8 + c2I) * DIMC + col;
                float2 r;
                r.x = D[mt][nt][half * 2 + 0] + bv.x;
                r.y = D[mt][nt][half * 2 + 1] + bv.y;
                *(float2*)&out[o] = r;
            }
        }
    }
}

// ---------------------------------------------------------------------------
extern "C" void kernel_launch(void* const* d_in, const int* in_sizes, int n_in,
                              void* d_out, int out_size) {
    (void)in_sizes; (void)n_in; (void)out_size;
    const float* qkv    = (const float*)d_in[0];
    const float* scale  = (const float*)d_in[1];
    const float* proj_w = (const float*)d_in[2];
    const float* proj_b = (const float*)d_in[3];
    const float* conv_w = (const float*)d_in[4];
    const float* conv_b = (const float*)d_in[5];
    float* out = (float*)d_out;

    const float* v = qkv + 2ULL * BATCH * LTOK * DIMC;

    prep_k<<<dim3(64, NWTOT), 256>>>(qkv);
    lepe_kernel<<<dim3(16, NWTOT), 256>>>(v, conv_w, conv_b);

    cudaFuncSetAttribute(attn_hmma, cudaFuncAttributeMaxDynamicSharedMemorySize,
                         ATTN_SMEM_BYTES);
    attn_hmma<<<dim3(NWTOT, NH, 4), 256, ATTN_SMEM_BYTES>>>(qkv, scale);

    proj_hmma<<<dim3(DIMC / 128, (NWTOT * WIN) / 128), 256>>>(proj_w, proj_b, out);
}

// round 8
// speedup vs baseline: 8.9032x; 1.0734x over previous
#include <cuda_runtime.h>
#include <cuda_fp16.h>
#include <cstdint>

#define BATCH 8
#define RESO 64
#define DIMC 256
#define NH 8
#define HD 32
#define WIN 512
#define NWTOT 64
#define LTOK 4096
#define MROWS (NWTOT * WIN)          // 32768
#define PLANE ((size_t)MROWS * 40)   // halves per chunk-plane of g_xh

// ---------------------------------------------------------------------------
// Scratch (__device__ globals: allocation-free rule)
// ---------------------------------------------------------------------------
__device__ __align__(16) float  g_lepe[(size_t)MROWS * DIMC];
__device__ __align__(16) __half g_xh[(size_t)NH * PLANE];            // [chunk(=head)][row][40]
__device__ __align__(16) __half g_kh[(size_t)NWTOT * NH * WIN * 40]; // [w][n][key][40]
__device__ __align__(16) __half g_vt[(size_t)NWTOT * NH * 32 * 520]; // [w][n][d][520]
__device__ __align__(16) __half g_wh[(size_t)8 * DIMC * 40];         // [chunk][col][40]

// ---------------------------------------------------------------------------
// Helpers
// ---------------------------------------------------------------------------
__device__ __forceinline__ uint32_t ldu32(const __half* p) {
    return *reinterpret_cast<const uint32_t*>(p);
}
__device__ __forceinline__ uint32_t packh2(float x, float y) {
    __half2 h = __floats2half2_rn(x, y);
    return *reinterpret_cast<uint32_t*>(&h);
}
__device__ __forceinline__ uint32_t smem_u32(const void* p) {
    uint32_t a;
    asm("{ .reg .u64 t; cvta.to.shared.u64 t, %1; cvt.u32.u64 %0, t; }"
        : "=r"(a) : "l"(p));
    return a;
}
__device__ __forceinline__ void mma16816(float d[4], const uint32_t a[4],
                                         const uint32_t b[2]) {
    asm volatile(
        "mma.sync.aligned.m16n8k16.row.col.f32.f16.f16.f32 "
        "{%0,%1,%2,%3}, {%4,%5,%6,%7}, {%8,%9}, {%0,%1,%2,%3};\n"
        : "+f"(d[0]), "+f"(d[1]), "+f"(d[2]), "+f"(d[3])
        : "r"(a[0]), "r"(a[1]), "r"(a[2]), "r"(a[3]), "r"(b[0]), "r"(b[1]));
}
#define LDSM_X4(r0, r1, r2, r3, addr) \
    asm volatile("ldmatrix.sync.aligned.m8n8.x4.shared.b16 {%0,%1,%2,%3}, [%4];" \
                 : "=r"(r0), "=r"(r1), "=r"(r2), "=r"(r3) : "r"(addr))

// ---------------------------------------------------------------------------
// prep_k: K fp32 -> fp16 into padded smem-image layout [w][n][key][40]
// ---------------------------------------------------------------------------
__global__ __launch_bounds__(256) void prep_k(const float* __restrict__ qkv) {
    const float* kp = qkv + (size_t)BATCH * LTOK * DIMC;
    const int w = blockIdx.y, b = w >> 3, j = w & 7;
    const int tid = threadIdx.x;
    const int d = tid & 31, kloc = tid >> 5;
    const int key = blockIdx.x * 8 + kloc;
    const int rs = key >> 3, cs = key & 7;
    const float* src = kp + ((size_t)b * LTOK + rs * RESO + j * 8 + cs) * DIMC + d;
    __half* dst = g_kh + ((size_t)(w * NH) * WIN + key) * 40 + d;
    #pragma unroll
    for (int n = 0; n < NH; n++)
        dst[(size_t)n * WIN * 40] = __float2half_rn(src[n * 32]);
}

// ---------------------------------------------------------------------------
// prep_w: W fp32 -> fp16 into [chunk][col][40] padded layout
// ---------------------------------------------------------------------------
__global__ __launch_bounds__(256) void prep_w(const float* __restrict__ W) {
    const int c = blockIdx.x, k = threadIdx.x;
    g_wh[(size_t)(k >> 5) * (DIMC * 40) + c * 40 + (k & 31)] =
        __float2half_rn(W[(size_t)c * DIMC + k]);
}

// ---------------------------------------------------------------------------
// LePE: depthwise 3x3 conv on V windows (rolling register window).
// Also emits Vt fp16 [w][n][d][520] for attention.
// ---------------------------------------------------------------------------
__global__ __launch_bounds__(256) void lepe_kernel(const float* __restrict__ v,
                                                   const float* __restrict__ cw,
                                                   const float* __restrict__ cb) {
    const int slab = blockIdx.x;   // 0..15
    const int w = blockIdx.y;      // 0..63
    const int c = threadIdx.x;     // channel
    const int b = w >> 3, j = w & 7;
    const int n = c >> 5, d = c & 31;
    float wt[9];
    #pragma unroll
    for (int i = 0; i < 9; i++) wt[i] = cw[c * 9 + i];
    const float bias = cb[c];
    const int r0 = slab * 4;
    const float* base = v + ((size_t)b * LTOK + j * 8) * DIMC + c;
    float* outb = g_lepe + (size_t)w * WIN * DIMC + c;
    __half* vtb = g_vt + ((size_t)(w * NH + n) * 32 + d) * 520;

    float rows[3][8];
    #pragma unroll
    for (int cc = 0; cc < 8; cc++) {
        rows[0][cc] = (r0 == 0) ? 0.f : base[((size_t)(r0 - 1) * RESO + cc) * DIMC];
        rows[1][cc] = base[((size_t)r0 * RESO + cc) * DIMC];
    }
    #pragma unroll
    for (int rr = 0; rr < 4; rr++) {
        const int prv = rr % 3, cur = (rr + 1) % 3, nxt = (rr + 2) % 3;
        const int rn = r0 + rr + 1;
        #pragma unroll
        for (int cc = 0; cc < 8; cc++)
            rows[nxt][cc] = (rn >= RESO) ? 0.f : base[((size_t)rn * RESO + cc) * DIMC];
        const int rabs = r0 + rr;
        {
            union { uint4 u; __half h[8]; } pk;
            #pragma unroll
            for (int cc = 0; cc < 8; cc++) pk.h[cc] = __float2half_rn(rows[cur][cc]);
            *(uint4*)(vtb + rabs * 8) = pk.u;
        }
        #pragma unroll
        for (int cc = 0; cc < 8; cc++) {
            float acc = bias;
            if (cc > 0) {
                acc += rows[prv][cc - 1] * wt[0];
                acc += rows[cur][cc - 1] * wt[3];
                acc += rows[nxt][cc - 1] * wt[6];
            }
            acc += rows[prv][cc] * wt[1];
            acc += rows[cur][cc] * wt[4];
            acc += rows[nxt][cc] * wt[7];
            if (cc < 7) {
                acc += rows[prv][cc + 1] * wt[2];
                acc += rows[cur][cc + 1] * wt[5];
                acc += rows[nxt][cc + 1] * wt[8];
            }
            outb[(size_t)(rabs * 8 + cc) * DIMC] = acc;
        }
    }
}

// ---------------------------------------------------------------------------
// HMMA flash attention. CTA = (window, head, quarter). 8 warps x 16 query rows.
// ---------------------------------------------------------------------------
#define VTOo (512 * 40)          // halves
#define VTOBYTES (512 * 40 * 2)
#define ATTN_SMEM_BYTES ((512 * 40 + 32 * 520) * 2)

__global__ __launch_bounds__(256, 3) void attn_hmma(const float* __restrict__ qkv,
                                                    const float* __restrict__ scale_p) {
    extern __shared__ __half sm[];
    const int tid = threadIdx.x;
    const int w = blockIdx.x, n = blockIdx.y, z = blockIdx.z;
    const int b = w >> 3, j = w & 7;
    const float qscale = scale_p[0] * 1.44269504f;

    // ---- fill K & Vt by aligned vector copy ----
    {
        const uint4* gk = (const uint4*)(g_kh + (size_t)(w * NH + n) * WIN * 40);
        uint4* dk = (uint4*)sm;
        #pragma unroll
        for (int i = 0; i < 10; i++) dk[tid + i * 256] = gk[tid + i * 256];
        const uint4* gv = (const uint4*)(g_vt + (size_t)(w * NH + n) * 32 * 520);
        uint4* dv = (uint4*)(sm + VTOo);
        #pragma unroll
        for (int i = 0; i < 8; i++) dv[tid + i * 256] = gv[tid + i * 256];
        if (tid < 2080 - 2048) dv[tid + 2048] = gv[tid + 2048];
    }

    const int wid = tid >> 5, lane = tid & 31;
    const int g = lane >> 2, t2 = (lane & 3) * 2;
    const int m0 = z * 128 + wid * 16;
    const bool mzero = (j == 7) && ((g < 4) != ((lane & 3) < 2));

    // ---- persistent Q fragments ----
    uint32_t qh[2][4];
    #pragma unroll
    for (int rh = 0; rh < 2; rh++) {
        int row = m0 + g + rh * 8;
        int rs = row >> 3, cs = row & 7;
        const float* src = qkv + ((size_t)b * LTOK + rs * RESO + j * 8 + cs) * DIMC + n * HD;
        #pragma unroll
        for (int ks = 0; ks < 2; ks++) {
            #pragma unroll
            for (int ch = 0; ch < 2; ch++) {
                float2 f = *(const float2*)(src + ks * 16 + ch * 8 + t2);
                qh[ks][rh + ch * 2] = packh2(f.x * qscale, f.y * qscale);
            }
        }
    }
    __syncthreads();

    const uint32_t sb = smem_u32(sm);
    const uint32_t kconst = sb + (uint32_t)((lane & 7) * 80 + (lane >> 3) * 16);
    const uint32_t vconst = sb + VTOBYTES +
        (uint32_t)((((lane >> 4) * 8) + (lane & 7)) * 1040 + ((lane >> 3) & 1) * 16);

    float O[4][4];
    float lsl = 0.f, lsh = 0.f;
    #pragma unroll
    for (int nt = 0; nt < 4; nt++)
        #pragma unroll
        for (int e = 0; e < 4; e++) O[nt][e] = 0.f;

    #pragma unroll 4
    for (int step = 0; step < 32; step++) {
        float S[2][4];
        #pragma unroll
        for (int nt = 0; nt < 2; nt++)
            #pragma unroll
            for (int e = 0; e < 4; e++) S[nt][e] = 0.f;

        uint32_t kb[2][2][2];
        LDSM_X4(kb[0][0][0], kb[0][0][1], kb[0][1][0], kb[0][1][1],
                kconst + (uint32_t)step * 1280u);
        LDSM_X4(kb[1][0][0], kb[1][0][1], kb[1][1][0], kb[1][1][1],
                kconst + (uint32_t)step * 1280u + 640u);
        #pragma unroll
        for (int nt = 0; nt < 2; nt++)
            #pragma unroll
            for (int ks = 0; ks < 2; ks++)
                mma16816(S[nt], qh[ks], kb[nt][ks]);

        uint32_t pa[4];
        #pragma unroll
        for (int nt = 0; nt < 2; nt++) {
            float p0 = mzero ? 0.f : exp2f(S[nt][0]);
            float p1 = mzero ? 0.f : exp2f(S[nt][1]);
            float p2 = mzero ? 0.f : exp2f(S[nt][2]);
            float p3 = mzero ? 0.f : exp2f(S[nt][3]);
            lsl += p0 + p1;
            lsh += p2 + p3;
            pa[nt * 2 + 0] = packh2(p0, p1);
            pa[nt * 2 + 1] = packh2(p2, p3);
        }

        uint32_t vb[4][2];
        LDSM_X4(vb[0][0], vb[0][1], vb[1][0], vb[1][1],
                vconst + (uint32_t)step * 32u);
        LDSM_X4(vb[2][0], vb[2][1], vb[3][0], vb[3][1],
                vconst + (uint32_t)step * 32u + 16640u);
        #pragma unroll
        for (int ntd = 0; ntd < 4; ntd++)
            mma16816(O[ntd], pa, vb[ntd]);
    }

    lsl += __shfl_xor_sync(0xffffffffu, lsl, 1);
    lsl += __shfl_xor_sync(0xffffffffu, lsl, 2);
    lsh += __shfl_xor_sync(0xffffffffu, lsh, 1);
    lsh += __shfl_xor_sync(0xffffffffu, lsh, 2);

    // ---- epilogue: O/lsum + lepe -> fp16 chunk-major padded g_xh ----
    const float il = 1.f / lsl, ih = 1.f / lsh;
    const int r0q = m0 + g;
    const size_t grow = (size_t)w * WIN + r0q;
    #pragma unroll
    for (int ntd = 0; ntd < 4; ntd++) {
        size_t l0 = grow * DIMC + n * HD + ntd * 8 + t2;
        size_t l1 = l0 + 8 * DIMC;
        size_t x0 = (size_t)n * PLANE + grow * 40 + ntd * 8 + t2;
        size_t x1 = x0 + 8 * 40;
        float2 e0 = *(const float2*)(g_lepe + l0);
        float2 e1 = *(const float2*)(g_lepe + l1);
        *(__half2*)(g_xh + x0) = __floats2half2_rn(O[ntd][0] * il + e0.x,
                                                   O[ntd][1] * il + e0.y);
        *(__half2*)(g_xh + x1) = __floats2half2_rn(O[ntd][2] * ih + e1.x,
                                                   O[ntd][3] * ih + e1.y);
    }
}

// ---------------------------------------------------------------------------
// Projection: out = x @ W^T + b. CTA tile 128m x 64n, 8 warps (4m x 2n),
// software-pipelined k-chunks, pure-memcpy smem fills from g_xh / g_wh.
// ---------------------------------------------------------------------------
__global__ __launch_bounds__(256, 2) void proj_hmma(const __half* __restrict__ dummy,
                                                    const float* __restrict__ bias,
                                                    float* __restrict__ out) {
    __shared__ __half Ah[2][128 * 40];
    __shared__ __half Bh[2][64 * 40];
    const int tid = threadIdx.x;
    const int m0 = blockIdx.y * 128, n0 = blockIdx.x * 64;
    const int wid = tid >> 5, lane = tid & 31;
    const int g = lane >> 2, t2 = (lane & 3) * 2;
    const int wm = (wid >> 1) * 32, wn = (wid & 1) * 32;

    float D[2][4][4];
    #pragma unroll
    for (int mt = 0; mt < 2; mt++)
        #pragma unroll
        for (int nt = 0; nt < 4; nt++)
            #pragma unroll
            for (int e = 0; e < 4; e++) D[mt][nt][e] = 0.f;

    uint4 ra[3], rb[2];
    auto ldg_chunk = [&](int c) {
        const uint4* As = (const uint4*)(g_xh + (size_t)c * PLANE + (size_t)m0 * 40);
        #pragma unroll
        for (int i = 0; i < 3; i++) {
            int idx = tid + i * 256;
            if (idx < 640) ra[i] = As[idx];
        }
        const uint4* Bs = (const uint4*)(g_wh + (size_t)c * (DIMC * 40) + (size_t)n0 * 40);
        #pragma unroll
        for (int i = 0; i < 2; i++) {
            int idx = tid + i * 256;
            if (idx < 320) rb[i] = Bs[idx];
        }
    };
    auto sts_chunk = [&](int buf) {
        uint4* Ad = (uint4*)Ah[buf];
        #pragma unroll
        for (int i = 0; i < 3; i++) {
            int idx = tid + i * 256;
            if (idx < 640) Ad[idx] = ra[i];
        }
        uint4* Bd = (uint4*)Bh[buf];
        #pragma unroll
        for (int i = 0; i < 2; i++) {
            int idx = tid + i * 256;
            if (idx < 320) Bd[idx] = rb[i];
        }
    };

    ldg_chunk(0);
    sts_chunk(0);
    __syncthreads();

    #pragma unroll
    for (int c = 0; c < 8; c++) {
        if (c < 7) ldg_chunk(c + 1);
        const __half* Ab = Ah[c & 1];
        const __half* Bb = Bh[c & 1];

        uint32_t bb[4][2][2];
        #pragma unroll
        for (int nt = 0; nt < 4; nt++)
            #pragma unroll
            for (int ks = 0; ks < 2; ks++) {
                const __half* p0 = Bb + (wn + nt * 8 + g) * 40 + ks * 16 + t2;
                bb[nt][ks][0] = ldu32(p0);
                bb[nt][ks][1] = ldu32(p0 + 8);
            }
        uint32_t a[2][2][4];
        #pragma unroll
        for (int mt = 0; mt < 2; mt++)
            #pragma unroll
            for (int ks = 0; ks < 2; ks++) {
                const __half* p0 = Ab + (wm + mt * 16 + g) * 40 + ks * 16 + t2;
                a[mt][ks][0] = ldu32(p0);
                a[mt][ks][1] = ldu32(p0 + 8 * 40);
                a[mt][ks][2] = ldu32(p0 + 8);
                a[mt][ks][3] = ldu32(p0 + 8 * 40 + 8);
            }
        #pragma unroll
        for (int mt = 0; mt < 2; mt++)
            #pragma unroll
            for (int nt = 0; nt < 4; nt++)
                #pragma unroll
                for (int ks = 0; ks < 2; ks++)
                    mma16816(D[mt][nt], a[mt][ks], bb[nt][ks]);

        if (c < 7) {
            __syncthreads();
            sts_chunk((c + 1) & 1);
            __syncthreads();
        }
    }

    // ---- scatter epilogue with bias ----
    #pragma unroll
    for (int mt = 0; mt < 2; mt++) {
        #pragma unroll
        for (int nt = 0; nt < 4; nt++) {
            int col = n0 + wn + nt * 8 + t2;
            float2 bv = *(const float2*)&bias[col];
            #pragma unroll
            for (int half = 0; half < 2; half++) {
                int mrow = m0 + wm + mt * 16 + g + half * 8;
                int wI = mrow >> 9, t = mrow & 511;
                int bI = wI >> 3, jI = wI & 7;
                int rI = t >> 3, c2I = t & 7;
                size_t o = ((size_t)bI * LTOK + rI * RESO + jI * 8 + c2I) * DIMC + col;
                float2 r;
                r.x = D[mt][nt][half * 2 + 0] + bv.x;
                r.y = D[mt][nt][half * 2 + 1] + bv.y;
                *(float2*)&out[o] = r;
            }
        }
    }
}

// ---------------------------------------------------------------------------
extern "C" void kernel_launch(void* const* d_in, const int* in_sizes, int n_in,
                              void* d_out, int out_size) {
    (void)in_sizes; (void)n_in; (void)out_size;
    const float* qkv    = (const float*)d_in[0];
    const float* scale  = (const float*)d_in[1];
    const float* proj_w = (const float*)d_in[2];
    const float* proj_b = (const float*)d_in[3];
    const float* conv_w = (const float*)d_in[4];
    const float* conv_b = (const float*)d_in[5];
    float* out = (float*)d_out;

    const float* v = qkv + 2ULL * BATCH * LTOK * DIMC;

    prep_k<<<dim3(64, NWTOT), 256>>>(qkv);
    prep_w<<<DIMC, 256>>>(proj_w);
    lepe_kernel<<<dim3(16, NWTOT), 256>>>(v, conv_w, conv_b);

    cudaFuncSetAttribute(attn_hmma, cudaFuncAttributeMaxDynamicSharedMemorySize,
                         ATTN_SMEM_BYTES);
    attn_hmma<<<dim3(NWTOT, NH, 4), 256, ATTN_SMEM_BYTES>>>(qkv, scale);

    proj_hmma<<<dim3(DIMC / 64, MROWS / 128), 256>>>(nullptr, proj_b, out);
}

// round 9
// speedup vs baseline: 11.4764x; 1.2890x over previous
#include <cuda_runtime.h>
#include <cuda_fp16.h>
#include <cstdint>

#define BATCH 8
#define RESO 64
#define DIMC 256
#define NH 8
#define HD 32
#define WIN 512
#define NWTOT 64
#define LTOK 4096
#define MROWS (NWTOT * WIN)          // 32768
#define PLANE ((size_t)MROWS * 40)   // halves per chunk-plane of g_xh

// ---------------------------------------------------------------------------
// Scratch (__device__ globals: allocation-free rule)
// ---------------------------------------------------------------------------
__device__ __align__(16) float  g_lepe[(size_t)MROWS * DIMC];
__device__ __align__(16) __half g_xh[(size_t)NH * PLANE];            // [chunk(=head)][row][40]
__device__ __align__(16) __half g_kh[(size_t)NWTOT * NH * WIN * 40]; // [w][n][key][40]
__device__ __align__(16) __half g_vt[(size_t)NWTOT * NH * 32 * 520]; // [w][n][d][520]
__device__ __align__(16) __half g_wh[(size_t)8 * DIMC * 40];         // [chunk][col][40]

// ---------------------------------------------------------------------------
// Helpers
// ---------------------------------------------------------------------------
__device__ __forceinline__ uint32_t packh2(float x, float y) {
    __half2 h = __floats2half2_rn(x, y);
    return *reinterpret_cast<uint32_t*>(&h);
}
__device__ __forceinline__ uint32_t smem_u32(const void* p) {
    uint32_t a;
    asm("{ .reg .u64 t; cvta.to.shared.u64 t, %1; cvt.u32.u64 %0, t; }"
        : "=r"(a) : "l"(p));
    return a;
}
__device__ __forceinline__ void mma16816(float d[4], const uint32_t a[4],
                                         const uint32_t b[2]) {
    asm volatile(
        "mma.sync.aligned.m16n8k16.row.col.f32.f16.f16.f32 "
        "{%0,%1,%2,%3}, {%4,%5,%6,%7}, {%8,%9}, {%0,%1,%2,%3};\n"
        : "+f"(d[0]), "+f"(d[1]), "+f"(d[2]), "+f"(d[3])
        : "r"(a[0]), "r"(a[1]), "r"(a[2]), "r"(a[3]), "r"(b[0]), "r"(b[1]));
}
#define LDSM_X4(r0, r1, r2, r3, addr) \
    asm volatile("ldmatrix.sync.aligned.m8n8.x4.shared.b16 {%0,%1,%2,%3}, [%4];" \
                 : "=r"(r0), "=r"(r1), "=r"(r2), "=r"(r3) : "r"(addr))
#define EX2F16X2(d, s) \
    asm("ex2.approx.f16x2 %0, %1;" : "=r"(d) : "r"(s))
#define CP_ASYNC16(dst, src) \
    asm volatile("cp.async.cg.shared.global [%0], [%1], 16;" :: "r"(dst), "l"(src))
#define CP_COMMIT() asm volatile("cp.async.commit_group;")

// ---------------------------------------------------------------------------
// prep_k: K fp32 -> fp16 into padded smem-image layout [w][n][key][40]
// ---------------------------------------------------------------------------
__global__ __launch_bounds__(256) void prep_k(const float* __restrict__ qkv) {
    const float* kp = qkv + (size_t)BATCH * LTOK * DIMC;
    const int w = blockIdx.y, b = w >> 3, j = w & 7;
    const int tid = threadIdx.x;
    const int d = tid & 31, kloc = tid >> 5;
    const int key = blockIdx.x * 8 + kloc;
    const int rs = key >> 3, cs = key & 7;
    const float* src = kp + ((size_t)b * LTOK + rs * RESO + j * 8 + cs) * DIMC + d;
    __half* dst = g_kh + ((size_t)(w * NH) * WIN + key) * 40 + d;
    #pragma unroll
    for (int n = 0; n < NH; n++)
        dst[(size_t)n * WIN * 40] = __float2half_rn(src[n * 32]);
}

// ---------------------------------------------------------------------------
// prep_w: W fp32 -> fp16 into [chunk][col][40] padded layout
// ---------------------------------------------------------------------------
__global__ __launch_bounds__(256) void prep_w(const float* __restrict__ W) {
    const int c = blockIdx.x, k = threadIdx.x;
    g_wh[(size_t)(k >> 5) * (DIMC * 40) + c * 40 + (k & 31)] =
        __float2half_rn(W[(size_t)c * DIMC + k]);
}

// ---------------------------------------------------------------------------
// LePE: depthwise 3x3 conv on V windows (rolling register window).
// Also emits Vt fp16 [w][n][d][520] for attention.
// ---------------------------------------------------------------------------
__global__ __launch_bounds__(256) void lepe_kernel(const float* __restrict__ v,
                                                   const float* __restrict__ cw,
                                                   const float* __restrict__ cb) {
    const int slab = blockIdx.x;   // 0..15
    const int w = blockIdx.y;      // 0..63
    const int c = threadIdx.x;     // channel
    const int b = w >> 3, j = w & 7;
    const int n = c >> 5, d = c & 31;
    float wt[9];
    #pragma unroll
    for (int i = 0; i < 9; i++) wt[i] = cw[c * 9 + i];
    const float bias = cb[c];
    const int r0 = slab * 4;
    const float* base = v + ((size_t)b * LTOK + j * 8) * DIMC + c;
    float* outb = g_lepe + (size_t)w * WIN * DIMC + c;
    __half* vtb = g_vt + ((size_t)(w * NH + n) * 32 + d) * 520;

    float rows[3][8];
    #pragma unroll
    for (int cc = 0; cc < 8; cc++) {
        rows[0][cc] = (r0 == 0) ? 0.f : base[((size_t)(r0 - 1) * RESO + cc) * DIMC];
        rows[1][cc] = base[((size_t)r0 * RESO + cc) * DIMC];
    }
    #pragma unroll
    for (int rr = 0; rr < 4; rr++) {
        const int prv = rr % 3, cur = (rr + 1) % 3, nxt = (rr + 2) % 3;
        const int rn = r0 + rr + 1;
        #pragma unroll
        for (int cc = 0; cc < 8; cc++)
            rows[nxt][cc] = (rn >= RESO) ? 0.f : base[((size_t)rn * RESO + cc) * DIMC];
        const int rabs = r0 + rr;
        {
            union { uint4 u; __half h[8]; } pk;
            #pragma unroll
            for (int cc = 0; cc < 8; cc++) pk.h[cc] = __float2half_rn(rows[cur][cc]);
            *(uint4*)(vtb + rabs * 8) = pk.u;
        }
        #pragma unroll
        for (int cc = 0; cc < 8; cc++) {
            float acc = bias;
            if (cc > 0) {
                acc += rows[prv][cc - 1] * wt[0];
                acc += rows[cur][cc - 1] * wt[3];
                acc += rows[nxt][cc - 1] * wt[6];
            }
            acc += rows[prv][cc] * wt[1];
            acc += rows[cur][cc] * wt[4];
            acc += rows[nxt][cc] * wt[7];
            if (cc < 7) {
                acc += rows[prv][cc + 1] * wt[2];
                acc += rows[cur][cc + 1] * wt[5];
                acc += rows[nxt][cc + 1] * wt[8];
            }
            outb[(size_t)(rabs * 8 + cc) * DIMC] = acc;
        }
    }
}

// ---------------------------------------------------------------------------
// HMMA flash attention. CTA = (window, head, half). 8 warps x 32 query rows.
// fp16 exp (ex2.f16x2); row sums via ones-MMA (fp32, shared rounding with PV).
// smem: Kh [512][40] + Vt [32][520] = 72.5 KB -> 2 CTAs/SM.
// ---------------------------------------------------------------------------
#define VTOo (512 * 40)          // halves
#define VTOBYTES (512 * 40 * 2)
#define ATTN_SMEM_BYTES ((512 * 40 + 32 * 520) * 2)

__global__ __launch_bounds__(256, 2) void attn_hmma(const float* __restrict__ qkv,
                                                    const float* __restrict__ scale_p) {
    extern __shared__ __half sm[];
    const int tid = threadIdx.x;
    const int w = blockIdx.x, n = blockIdx.y, z = blockIdx.z;
    const int b = w >> 3, j = w & 7;
    const float qscale = scale_p[0] * 1.44269504f;

    // ---- fill K & Vt by aligned vector copy ----
    {
        const uint4* gk = (const uint4*)(g_kh + (size_t)(w * NH + n) * WIN * 40);
        uint4* dk = (uint4*)sm;
        #pragma unroll
        for (int i = 0; i < 10; i++) dk[tid + i * 256] = gk[tid + i * 256];
        const uint4* gv = (const uint4*)(g_vt + (size_t)(w * NH + n) * 32 * 520);
        uint4* dv = (uint4*)(sm + VTOo);
        #pragma unroll
        for (int i = 0; i < 8; i++) dv[tid + i * 256] = gv[tid + i * 256];
        if (tid < 2080 - 2048) dv[tid + 2048] = gv[tid + 2048];
    }

    const int wid = tid >> 5, lane = tid & 31;
    const int g = lane >> 2, t2 = (lane & 3) * 2;
    const int m0 = z * 256 + wid * 32;
    const bool mzero = (j == 7) && ((g < 4) != ((lane & 3) < 2));

    // ---- persistent Q fragments (2 m-tiles, fp16, scaled) ----
    uint32_t qh[2][2][4];
    #pragma unroll
    for (int mt = 0; mt < 2; mt++) {
        #pragma unroll
        for (int rh = 0; rh < 2; rh++) {
            int row = m0 + mt * 16 + g + rh * 8;
            int rs = row >> 3, cs = row & 7;
            const float* src = qkv + ((size_t)b * LTOK + rs * RESO + j * 8 + cs) * DIMC + n * HD;
            #pragma unroll
            for (int ks = 0; ks < 2; ks++) {
                #pragma unroll
                for (int ch = 0; ch < 2; ch++) {
                    float2 f = *(const float2*)(src + ks * 16 + ch * 8 + t2);
                    qh[mt][ks][rh + ch * 2] = packh2(f.x * qscale, f.y * qscale);
                }
            }
        }
    }
    __syncthreads();

    const uint32_t sb = smem_u32(sm);
    const uint32_t kconst = sb + (uint32_t)((lane & 7) * 80 + (lane >> 3) * 16);
    const uint32_t vconst = sb + VTOBYTES +
        (uint32_t)((((lane >> 4) * 8) + (lane & 7)) * 1040 + ((lane >> 3) & 1) * 16);
    const uint32_t onesb[2] = {0x3C003C00u, 0x3C003C00u};

    float O[2][4][4];
    float D1[2][4];
    #pragma unroll
    for (int mt = 0; mt < 2; mt++) {
        #pragma unroll
        for (int e = 0; e < 4; e++) D1[mt][e] = 0.f;
        #pragma unroll
        for (int nt = 0; nt < 4; nt++)
            #pragma unroll
            for (int e = 0; e < 4; e++) O[mt][nt][e] = 0.f;
    }

    #pragma unroll 4
    for (int step = 0; step < 32; step++) {
        float S[2][2][4];
        #pragma unroll
        for (int mt = 0; mt < 2; mt++)
            #pragma unroll
            for (int nt = 0; nt < 2; nt++)
                #pragma unroll
                for (int e = 0; e < 4; e++) S[mt][nt][e] = 0.f;

        uint32_t kb[2][2][2];
        LDSM_X4(kb[0][0][0], kb[0][0][1], kb[0][1][0], kb[0][1][1],
                kconst + (uint32_t)step * 1280u);
        LDSM_X4(kb[1][0][0], kb[1][0][1], kb[1][1][0], kb[1][1][1],
                kconst + (uint32_t)step * 1280u + 640u);
        #pragma unroll
        for (int mt = 0; mt < 2; mt++)
            #pragma unroll
            for (int nt = 0; nt < 2; nt++)
                #pragma unroll
                for (int ks = 0; ks < 2; ks++)
                    mma16816(S[mt][nt], qh[mt][ks], kb[nt][ks]);

        // ---- softmax: pack S -> fp16x2, ex2 in fp16 ----
        uint32_t pa[2][4];
        #pragma unroll
        for (int mt = 0; mt < 2; mt++) {
            #pragma unroll
            for (int nt = 0; nt < 2; nt++) {
                uint32_t s01 = packh2(S[mt][nt][0], S[mt][nt][1]);
                uint32_t s23 = packh2(S[mt][nt][2], S[mt][nt][3]);
                uint32_t p01, p23;
                EX2F16X2(p01, s01);
                EX2F16X2(p23, s23);
                pa[mt][nt * 2 + 0] = mzero ? 0u : p01;
                pa[mt][nt * 2 + 1] = mzero ? 0u : p23;
            }
        }

        uint32_t vb[4][2];
        LDSM_X4(vb[0][0], vb[0][1], vb[1][0], vb[1][1],
                vconst + (uint32_t)step * 32u);
        LDSM_X4(vb[2][0], vb[2][1], vb[3][0], vb[3][1],
                vconst + (uint32_t)step * 32u + 16640u);
        #pragma unroll
        for (int mt = 0; mt < 2; mt++) {
            #pragma unroll
            for (int ntd = 0; ntd < 4; ntd++)
                mma16816(O[mt][ntd], pa[mt], vb[ntd]);
            mma16816(D1[mt], pa[mt], onesb);   // row sums
        }
    }

    // ---- epilogue: O/lsum + lepe -> fp16 chunk-major padded g_xh ----
    #pragma unroll
    for (int mt = 0; mt < 2; mt++) {
        const float il = 1.f / D1[mt][0];   // rows g+..
        const float ih = 1.f / D1[mt][2];   // rows g+8..
        const int r0q = m0 + mt * 16 + g;
        const size_t grow = (size_t)w * WIN + r0q;
        #pragma unroll
        for (int ntd = 0; ntd < 4; ntd++) {
            size_t l0 = grow * DIMC + n * HD + ntd * 8 + t2;
            size_t l1 = l0 + 8 * DIMC;
            size_t x0 = (size_t)n * PLANE + grow * 40 + ntd * 8 + t2;
            size_t x1 = x0 + 8 * 40;
            float2 e0 = *(const float2*)(g_lepe + l0);
            float2 e1 = *(const float2*)(g_lepe + l1);
            *(__half2*)(g_xh + x0) = __floats2half2_rn(O[mt][ntd][0] * il + e0.x,
                                                       O[mt][ntd][1] * il + e0.y);
            *(__half2*)(g_xh + x1) = __floats2half2_rn(O[mt][ntd][2] * ih + e1.x,
                                                       O[mt][ntd][3] * ih + e1.y);
        }
    }
}

// ---------------------------------------------------------------------------
// Projection: out = x @ W^T + b. CTA 128m x 64n, 8 warps (4m x 2n) 32x32 tiles.
// cp.async 4-stage pipeline (prefetch 3), one sync/chunk, ldmatrix fragments.
// ---------------------------------------------------------------------------
#define PROJ_SMEM_BYTES (4 * (128 * 40 + 64 * 40) * 2)   // 61440

__global__ __launch_bounds__(256, 2) void proj_hmma(const float* __restrict__ bias,
                                                    float* __restrict__ out) {
    extern __shared__ __half psm[];
    const int tid = threadIdx.x;
    const int m0 = blockIdx.y * 128, n0 = blockIdx.x * 64;
    const int wid = tid >> 5, lane = tid & 31;
    const int g = lane >> 2, t2 = (lane & 3) * 2;
    const int wm = (wid >> 1) * 32, wn = (wid & 1) * 32;
    const uint32_t sb = smem_u32(psm);

    auto fill = [&](int c, int s) {
        uint32_t abase = sb + (uint32_t)s * 10240u;
        const __half* asrc = g_xh + (size_t)c * PLANE + (size_t)m0 * 40;
        #pragma unroll
        for (int i = 0; i < 3; i++) {
            int idx = tid + i * 256;
            if (idx < 640) CP_ASYNC16(abase + idx * 16, asrc + idx * 8);
        }
        uint32_t bbase = sb + 40960u + (uint32_t)s * 5120u;
        const __half* bsrc = g_wh + (size_t)c * (DIMC * 40) + (size_t)n0 * 40;
        #pragma unroll
        for (int i = 0; i < 2; i++) {
            int idx = tid + i * 256;
            if (idx < 320) CP_ASYNC16(bbase + idx * 16, bsrc + idx * 8);
        }
        CP_COMMIT();
    };

    float D[2][4][4];
    #pragma unroll
    for (int mt = 0; mt < 2; mt++)
        #pragma unroll
        for (int nt = 0; nt < 4; nt++)
            #pragma unroll
            for (int e = 0; e < 4; e++) D[mt][nt][e] = 0.f;

    fill(0, 0); fill(1, 1); fill(2, 2);

    const uint32_t aoff = (uint32_t)(wm * 80 + (lane & 15) * 80 + (lane >> 4) * 16);
    const uint32_t boff = (uint32_t)(40960 + (wn + (lane & 7)) * 80 + (lane >> 3) * 16);

    #pragma unroll
    for (int c = 0; c < 8; c++) {
        if (c <= 5)      asm volatile("cp.async.wait_group 2;");
        else if (c == 6) asm volatile("cp.async.wait_group 1;");
        else             asm volatile("cp.async.wait_group 0;");
        __syncthreads();
        if (c + 3 < 8) fill(c + 3, (c + 3) & 3);

        const uint32_t aconst = sb + (uint32_t)(c & 3) * 10240u + aoff;
        const uint32_t bconst = sb + (uint32_t)(c & 3) * 5120u + boff;

        uint32_t a[2][2][4];
        #pragma unroll
        for (int mt = 0; mt < 2; mt++)
            #pragma unroll
            for (int ks = 0; ks < 2; ks++)
                LDSM_X4(a[mt][ks][0], a[mt][ks][1], a[mt][ks][2], a[mt][ks][3],
                        aconst + (uint32_t)(mt * 1280 + ks * 32));
        uint32_t bb[4][2][2];
        #pragma unroll
        for (int nt = 0; nt < 4; nt++)
            LDSM_X4(bb[nt][0][0], bb[nt][0][1], bb[nt][1][0], bb[nt][1][1],
                    bconst + (uint32_t)(nt * 640));
        #pragma unroll
        for (int mt = 0; mt < 2; mt++)
            #pragma unroll
            for (int nt = 0; nt < 4; nt++)
                #pragma unroll
                for (int ks = 0; ks < 2; ks++)
                    mma16816(D[mt][nt], a[mt][ks], bb[nt][ks]);
    }

    // ---- scatter epilogue with bias ----
    #pragma unroll
    for (int mt = 0; mt < 2; mt++) {
        #pragma unroll
        for (int nt = 0; nt < 4; nt++) {
            int col = n0 + wn + nt * 8 + t2;
            float2 bv = *(const float2*)&bias[col];
            #pragma unroll
            for (int half = 0; half < 2; half++) {
                int mrow = m0 + wm + mt * 16 + g + half * 8;
                int wI = mrow >> 9, t = mrow & 511;
                int bI = wI >> 3, jI = wI & 7;
                int rI = t >> 3, c2I = t & 7;
                size_t o = ((size_t)bI * LTOK + rI * RESO + jI * 8 + c2I) * DIMC + col;
                float2 r;
                r.x = D[mt][nt][half * 2 + 0] + bv.x;
                r.y = D[mt][nt][half * 2 + 1] + bv.y;
                *(float2*)&out[o] = r;
            }
        }
    }
}

// ---------------------------------------------------------------------------
extern "C" void kernel_launch(void* const* d_in, const int* in_sizes, int n_in,
                              void* d_out, int out_size) {
    (void)in_sizes; (void)n_in; (void)out_size;
    const float* qkv    = (const float*)d_in[0];
    const float* scale  = (const float*)d_in[1];
    const float* proj_w = (const float*)d_in[2];
    const float* proj_b = (const float*)d_in[3];
    const float* conv_w = (const float*)d_in[4];
    const float* conv_b = (const float*)d_in[5];
    float* out = (float*)d_out;

    const float* v = qkv + 2ULL * BATCH * LTOK * DIMC;

    prep_k<<<dim3(64, NWTOT), 256>>>(qkv);
    prep_w<<<DIMC, 256>>>(proj_w);
    lepe_kernel<<<dim3(16, NWTOT), 256>>>(v, conv_w, conv_b);

    cudaFuncSetAttribute(attn_hmma, cudaFuncAttributeMaxDynamicSharedMemorySize,
                         ATTN_SMEM_BYTES);
    attn_hmma<<<dim3(NWTOT, NH, 2), 256, ATTN_SMEM_BYTES>>>(qkv, scale);

    cudaFuncSetAttribute(proj_hmma, cudaFuncAttributeMaxDynamicSharedMemorySize,
                         PROJ_SMEM_BYTES);
    proj_hmma<<<dim3(DIMC / 64, MROWS / 128), 256, PROJ_SMEM_BYTES>>>(proj_b, out);
}

// round 10
// speedup vs baseline: 12.4895x; 1.0883x over previous
#include <cuda_runtime.h>
#include <cuda_fp16.h>
#include <cstdint>

#define BATCH 8
#define RESO 64
#define DIMC 256
#define NH 8
#define HD 32
#define WIN 512
#define NWTOT 64
#define LTOK 4096
#define MROWS (NWTOT * WIN)          // 32768
#define PLANE ((size_t)MROWS * 40)   // halves per chunk-plane of g_xh

// ---------------------------------------------------------------------------
// Scratch (__device__ globals: allocation-free rule)
// ---------------------------------------------------------------------------
__device__ __align__(16) __half g_lepe[(size_t)MROWS * DIMC];
__device__ __align__(16) __half g_xh[(size_t)NH * PLANE];            // [chunk(=head)][row][40]
__device__ __align__(16) __half g_kh[(size_t)NWTOT * NH * WIN * 40]; // [w][n][key][40]
__device__ __align__(16) __half g_vt[(size_t)NWTOT * NH * 32 * 520]; // [w][n][d][520]
__device__ __align__(16) __half g_wh[(size_t)8 * DIMC * 40];         // [chunk][col][40]

// ---------------------------------------------------------------------------
// Helpers
// ---------------------------------------------------------------------------
__device__ __forceinline__ uint32_t packh2(float x, float y) {
    __half2 h = __floats2half2_rn(x, y);
    return *reinterpret_cast<uint32_t*>(&h);
}
__device__ __forceinline__ uint32_t smem_u32(const void* p) {
    uint32_t a;
    asm("{ .reg .u64 t; cvta.to.shared.u64 t, %1; cvt.u32.u64 %0, t; }"
        : "=r"(a) : "l"(p));
    return a;
}
__device__ __forceinline__ void mma16816(float d[4], const uint32_t a[4],
                                         const uint32_t b[2]) {
    asm volatile(
        "mma.sync.aligned.m16n8k16.row.col.f32.f16.f16.f32 "
        "{%0,%1,%2,%3}, {%4,%5,%6,%7}, {%8,%9}, {%0,%1,%2,%3};\n"
        : "+f"(d[0]), "+f"(d[1]), "+f"(d[2]), "+f"(d[3])
        : "r"(a[0]), "r"(a[1]), "r"(a[2]), "r"(a[3]), "r"(b[0]), "r"(b[1]));
}
#define LDSM_X4(r0, r1, r2, r3, addr) \
    asm volatile("ldmatrix.sync.aligned.m8n8.x4.shared.b16 {%0,%1,%2,%3}, [%4];" \
                 : "=r"(r0), "=r"(r1), "=r"(r2), "=r"(r3) : "r"(addr))
#define EX2F16X2(d, s) \
    asm("ex2.approx.f16x2 %0, %1;" : "=r"(d) : "r"(s))
#define CP_ASYNC16(dst, src) \
    asm volatile("cp.async.cg.shared.global [%0], [%1], 16;" :: "r"(dst), "l"(src))
#define CP_COMMIT() asm volatile("cp.async.commit_group;")

// ---------------------------------------------------------------------------
// Fused prep: region split by flat blockIdx.x
//   [0, 1024)    lepe (depthwise 3x3 conv, fp16 out) + Vt fp16 emit
//   [1024, 3072) prep_k: K fp32 -> fp16 [w][n][key][40]
//   [3072, 3104) prep_w: W fp32 -> fp16 [chunk][col][40]
// ---------------------------------------------------------------------------
__global__ __launch_bounds__(256) void prep_fused(const float* __restrict__ qkv,
                                                  const float* __restrict__ W,
                                                  const float* __restrict__ cw,
                                                  const float* __restrict__ cb) {
    const int bid = blockIdx.x, tid = threadIdx.x;

    if (bid < 1024) {
        // ---- LePE + Vt ----
        const int slab = bid & 15, w = bid >> 4;
        const int c = tid;
        const int b = w >> 3, j = w & 7;
        const int n = c >> 5, d = c & 31;
        const float* v = qkv + 2ULL * BATCH * LTOK * DIMC;
        float wt[9];
        #pragma unroll
        for (int i = 0; i < 9; i++) wt[i] = cw[c * 9 + i];
        const float bias = cb[c];
        const int r0 = slab * 4;
        const float* base = v + ((size_t)b * LTOK + j * 8) * DIMC + c;
        __half* outb = g_lepe + (size_t)w * WIN * DIMC + c;
        __half* vtb = g_vt + ((size_t)(w * NH + n) * 32 + d) * 520;

        float rows[3][8];
        #pragma unroll
        for (int cc = 0; cc < 8; cc++) {
            rows[0][cc] = (r0 == 0) ? 0.f : base[((size_t)(r0 - 1) * RESO + cc) * DIMC];
            rows[1][cc] = base[((size_t)r0 * RESO + cc) * DIMC];
        }
        #pragma unroll
        for (int rr = 0; rr < 4; rr++) {
            const int prv = rr % 3, cur = (rr + 1) % 3, nxt = (rr + 2) % 3;
            const int rn = r0 + rr + 1;
            #pragma unroll
            for (int cc = 0; cc < 8; cc++)
                rows[nxt][cc] = (rn >= RESO) ? 0.f : base[((size_t)rn * RESO + cc) * DIMC];
            const int rabs = r0 + rr;
            {
                union { uint4 u; __half h[8]; } pk;
                #pragma unroll
                for (int cc = 0; cc < 8; cc++) pk.h[cc] = __float2half_rn(rows[cur][cc]);
                *(uint4*)(vtb + rabs * 8) = pk.u;
            }
            #pragma unroll
            for (int cc = 0; cc < 8; cc++) {
                float acc = bias;
                if (cc > 0) {
                    acc += rows[prv][cc - 1] * wt[0];
                    acc += rows[cur][cc - 1] * wt[3];
                    acc += rows[nxt][cc - 1] * wt[6];
                }
                acc += rows[prv][cc] * wt[1];
                acc += rows[cur][cc] * wt[4];
                acc += rows[nxt][cc] * wt[7];
                if (cc < 7) {
                    acc += rows[prv][cc + 1] * wt[2];
                    acc += rows[cur][cc + 1] * wt[5];
                    acc += rows[nxt][cc + 1] * wt[8];
                }
                outb[(size_t)(rabs * 8 + cc) * DIMC] = __float2half_rn(acc);
            }
        }
    } else if (bid < 3072) {
        // ---- prep_k (vectorized float2 -> half2) ----
        const float* kp = qkv + (size_t)BATCH * LTOK * DIMC;
        const int idx = bid - 1024;                 // 0..2047
        const int kloc = tid >> 4, dp = tid & 15;   // 16 keys x 16 d-pairs
        const int gkey = idx * 16 + kloc;
        const int w = gkey >> 9, key = gkey & 511;
        const int b = w >> 3, j = w & 7;
        const int rs = key >> 3, cs = key & 7;
        const float* src = kp + ((size_t)b * LTOK + rs * RESO + j * 8 + cs) * DIMC + dp * 2;
        __half* dst = g_kh + ((size_t)(w * NH) * WIN + key) * 40 + dp * 2;
        #pragma unroll
        for (int n = 0; n < NH; n++) {
            float2 f = *(const float2*)(src + n * 32);
            *(__half2*)(dst + (size_t)n * WIN * 40) = __floats2half2_rn(f.x, f.y);
        }
    } else {
        // ---- prep_w (vectorized 8 floats -> uint4 of halves) ----
        const int gid = (bid - 3072) * 256 + tid;   // 0..8191
        const int c = gid >> 5, k0 = (gid & 31) * 8;
        float4 w0 = *(const float4*)&W[(size_t)c * DIMC + k0];
        float4 w1 = *(const float4*)&W[(size_t)c * DIMC + k0 + 4];
        union { uint4 u; __half2 h[4]; } pk;
        pk.h[0] = __floats2half2_rn(w0.x, w0.y);
        pk.h[1] = __floats2half2_rn(w0.z, w0.w);
        pk.h[2] = __floats2half2_rn(w1.x, w1.y);
        pk.h[3] = __floats2half2_rn(w1.z, w1.w);
        *(uint4*)(g_wh + (size_t)(k0 >> 5) * (DIMC * 40) + c * 40 + (k0 & 31)) = pk.u;
    }
}

// ---------------------------------------------------------------------------
// HMMA flash attention. CTA = (window, head, half). 8 warps x 32 query rows.
// fp16 exp (ex2.f16x2); row sums via HADD2 + fp32 (quad-shuffle at end).
// smem: Kh [512][40] + Vt [32][520] = 72.5 KB -> 2 CTAs/SM.
// ---------------------------------------------------------------------------
#define VTOo (512 * 40)          // halves
#define VTOBYTES (512 * 40 * 2)
#define ATTN_SMEM_BYTES ((512 * 40 + 32 * 520) * 2)

__global__ __launch_bounds__(256, 2) void attn_hmma(const float* __restrict__ qkv,
                                                    const float* __restrict__ scale_p) {
    extern __shared__ __half sm[];
    const int tid = threadIdx.x;
    const int w = blockIdx.x, n = blockIdx.y, z = blockIdx.z;
    const int b = w >> 3, j = w & 7;
    const float qscale = scale_p[0] * 1.44269504f;

    // ---- fill K & Vt by aligned vector copy ----
    {
        const uint4* gk = (const uint4*)(g_kh + (size_t)(w * NH + n) * WIN * 40);
        uint4* dk = (uint4*)sm;
        #pragma unroll
        for (int i = 0; i < 10; i++) dk[tid + i * 256] = gk[tid + i * 256];
        const uint4* gv = (const uint4*)(g_vt + (size_t)(w * NH + n) * 32 * 520);
        uint4* dv = (uint4*)(sm + VTOo);
        #pragma unroll
        for (int i = 0; i < 8; i++) dv[tid + i * 256] = gv[tid + i * 256];
        if (tid < 2080 - 2048) dv[tid + 2048] = gv[tid + 2048];
    }

    const int wid = tid >> 5, lane = tid & 31;
    const int g = lane >> 2, t2 = (lane & 3) * 2;
    const int m0 = z * 256 + wid * 32;
    const bool mzero = (j == 7) && ((g < 4) != ((lane & 3) < 2));

    // ---- persistent Q fragments (2 m-tiles, fp16, scaled) ----
    uint32_t qh[2][2][4];
    #pragma unroll
    for (int mt = 0; mt < 2; mt++) {
        #pragma unroll
        for (int rh = 0; rh < 2; rh++) {
            int row = m0 + mt * 16 + g + rh * 8;
            int rs = row >> 3, cs = row & 7;
            const float* src = qkv + ((size_t)b * LTOK + rs * RESO + j * 8 + cs) * DIMC + n * HD;
            #pragma unroll
            for (int ks = 0; ks < 2; ks++) {
                #pragma unroll
                for (int ch = 0; ch < 2; ch++) {
                    float2 f = *(const float2*)(src + ks * 16 + ch * 8 + t2);
                    qh[mt][ks][rh + ch * 2] = packh2(f.x * qscale, f.y * qscale);
                }
            }
        }
    }
    __syncthreads();

    const uint32_t sb = smem_u32(sm);
    const uint32_t kconst = sb + (uint32_t)((lane & 7) * 80 + (lane >> 3) * 16);
    const uint32_t vconst = sb + VTOBYTES +
        (uint32_t)((((lane >> 4) * 8) + (lane & 7)) * 1040 + ((lane >> 3) & 1) * 16);

    float O[2][4][4];
    float lsl[2] = {0.f, 0.f}, lsh[2] = {0.f, 0.f};
    #pragma unroll
    for (int mt = 0; mt < 2; mt++)
        #pragma unroll
        for (int nt = 0; nt < 4; nt++)
            #pragma unroll
            for (int e = 0; e < 4; e++) O[mt][nt][e] = 0.f;

    #pragma unroll 4
    for (int step = 0; step < 32; step++) {
        float S[2][2][4];
        #pragma unroll
        for (int mt = 0; mt < 2; mt++)
            #pragma unroll
            for (int nt = 0; nt < 2; nt++)
                #pragma unroll
                for (int e = 0; e < 4; e++) S[mt][nt][e] = 0.f;

        uint32_t kb[2][2][2];
        LDSM_X4(kb[0][0][0], kb[0][0][1], kb[0][1][0], kb[0][1][1],
                kconst + (uint32_t)step * 1280u);
        LDSM_X4(kb[1][0][0], kb[1][0][1], kb[1][1][0], kb[1][1][1],
                kconst + (uint32_t)step * 1280u + 640u);
        #pragma unroll
        for (int mt = 0; mt < 2; mt++)
            #pragma unroll
            for (int nt = 0; nt < 2; nt++)
                #pragma unroll
                for (int ks = 0; ks < 2; ks++)
                    mma16816(S[mt][nt], qh[mt][ks], kb[nt][ks]);

        // ---- softmax: pack S -> fp16x2, ex2 in fp16; lsum via HADD2+fp32 ----
        uint32_t pa[2][4];
        #pragma unroll
        for (int mt = 0; mt < 2; mt++) {
            #pragma unroll
            for (int nt = 0; nt < 2; nt++) {
                uint32_t s01 = packh2(S[mt][nt][0], S[mt][nt][1]);
                uint32_t s23 = packh2(S[mt][nt][2], S[mt][nt][3]);
                uint32_t p01, p23;
                EX2F16X2(p01, s01);
                EX2F16X2(p23, s23);
                pa[mt][nt * 2 + 0] = mzero ? 0u : p01;
                pa[mt][nt * 2 + 1] = mzero ? 0u : p23;
            }
            __half2 tl = __hadd2(*(__half2*)&pa[mt][0], *(__half2*)&pa[mt][2]);
            __half2 th = __hadd2(*(__half2*)&pa[mt][1], *(__half2*)&pa[mt][3]);
            float2 fl = __half22float2(tl);
            float2 fh = __half22float2(th);
            lsl[mt] += fl.x + fl.y;
            lsh[mt] += fh.x + fh.y;
        }

        uint32_t vb[4][2];
        LDSM_X4(vb[0][0], vb[0][1], vb[1][0], vb[1][1],
                vconst + (uint32_t)step * 32u);
        LDSM_X4(vb[2][0], vb[2][1], vb[3][0], vb[3][1],
                vconst + (uint32_t)step * 32u + 16640u);
        #pragma unroll
        for (int mt = 0; mt < 2; mt++)
            #pragma unroll
            for (int ntd = 0; ntd < 4; ntd++)
                mma16816(O[mt][ntd], pa[mt], vb[ntd]);
    }

    // ---- quad reduction of row sums ----
    #pragma unroll
    for (int mt = 0; mt < 2; mt++) {
        lsl[mt] += __shfl_xor_sync(0xffffffffu, lsl[mt], 1);
        lsl[mt] += __shfl_xor_sync(0xffffffffu, lsl[mt], 2);
        lsh[mt] += __shfl_xor_sync(0xffffffffu, lsh[mt], 1);
        lsh[mt] += __shfl_xor_sync(0xffffffffu, lsh[mt], 2);
    }

    // ---- epilogue: O/lsum + lepe(fp16) -> fp16 chunk-major padded g_xh ----
    #pragma unroll
    for (int mt = 0; mt < 2; mt++) {
        const float il = 1.f / lsl[mt];
        const float ih = 1.f / lsh[mt];
        const int r0q = m0 + mt * 16 + g;
        const size_t grow = (size_t)w * WIN + r0q;
        #pragma unroll
        for (int ntd = 0; ntd < 4; ntd++) {
            size_t l0 = grow * DIMC + n * HD + ntd * 8 + t2;
            size_t l1 = l0 + 8 * DIMC;
            size_t x0 = (size_t)n * PLANE + grow * 40 + ntd * 8 + t2;
            size_t x1 = x0 + 8 * 40;
            float2 e0 = __half22float2(*(const __half2*)(g_lepe + l0));
            float2 e1 = __half22float2(*(const __half2*)(g_lepe + l1));
            *(__half2*)(g_xh + x0) = __floats2half2_rn(O[mt][ntd][0] * il + e0.x,
                                                       O[mt][ntd][1] * il + e0.y);
            *(__half2*)(g_xh + x1) = __floats2half2_rn(O[mt][ntd][2] * ih + e1.x,
                                                       O[mt][ntd][3] * ih + e1.y);
        }
    }
}

// ---------------------------------------------------------------------------
// Projection: out = x @ W^T + b. CTA 128m x 64n, 8 warps (4m x 2n) 32x32 tiles.
// cp.async 3-stage pipeline, one sync/chunk, ldmatrix fragments, 3 CTAs/SM.
// ---------------------------------------------------------------------------
#define PROJ_SMEM_BYTES (3 * (128 * 40 + 64 * 40) * 2)   // 46080

__global__ __launch_bounds__(256, 3) void proj_hmma(const float* __restrict__ bias,
                                                    float* __restrict__ out) {
    extern __shared__ __half psm[];
    const int tid = threadIdx.x;
    const int m0 = blockIdx.y * 128, n0 = blockIdx.x * 64;
    const int wid = tid >> 5, lane = tid & 31;
    const int g = lane >> 2, t2 = (lane & 3) * 2;
    const int wm = (wid >> 1) * 32, wn = (wid & 1) * 32;
    const uint32_t sb = smem_u32(psm);

    auto fill = [&](int c) {
        int s = c % 3;
        uint32_t abase = sb + (uint32_t)s * 10240u;
        const __half* asrc = g_xh + (size_t)c * PLANE + (size_t)m0 * 40;
        #pragma unroll
        for (int i = 0; i < 3; i++) {
            int idx = tid + i * 256;
            if (idx < 640) CP_ASYNC16(abase + idx * 16, asrc + idx * 8);
        }
        uint32_t bbase = sb + 30720u + (uint32_t)s * 5120u;
        const __half* bsrc = g_wh + (size_t)c * (DIMC * 40) + (size_t)n0 * 40;
        #pragma unroll
        for (int i = 0; i < 2; i++) {
            int idx = tid + i * 256;
            if (idx < 320) CP_ASYNC16(bbase + idx * 16, bsrc + idx * 8);
        }
        CP_COMMIT();
    };

    float D[2][4][4];
    #pragma unroll
    for (int mt = 0; mt < 2; mt++)
        #pragma unroll
        for (int nt = 0; nt < 4; nt++)
            #pragma unroll
            for (int e = 0; e < 4; e++) D[mt][nt][e] = 0.f;

    fill(0); fill(1);

    const uint32_t aoff = (uint32_t)(wm * 80 + (lane & 15) * 80 + (lane >> 4) * 16);
    const uint32_t boff = (uint32_t)(30720 + (wn + (lane & 7)) * 80 + (lane >> 3) * 16);

    #pragma unroll
    for (int c = 0; c < 8; c++) {
        if (c < 7) asm volatile("cp.async.wait_group 1;");
        else       asm volatile("cp.async.wait_group 0;");
        __syncthreads();
        if (c + 2 < 8) fill(c + 2);

        const uint32_t aconst = sb + (uint32_t)(c % 3) * 10240u + aoff;
        const uint32_t bconst = sb + (uint32_t)(c % 3) * 5120u + boff;

        uint32_t a[2][2][4];
        #pragma unroll
        for (int mt = 0; mt < 2; mt++)
            #pragma unroll
            for (int ks = 0; ks < 2; ks++)
                LDSM_X4(a[mt][ks][0], a[mt][ks][1], a[mt][ks][2], a[mt][ks][3],
                        aconst + (uint32_t)(mt * 1280 + ks * 32));
        uint32_t bb[4][2][2];
        #pragma unroll
        for (int nt = 0; nt < 4; nt++)
            LDSM_X4(bb[nt][0][0], bb[nt][0][1], bb[nt][1][0], bb[nt][1][1],
                    bconst + (uint32_t)(nt * 640));
        #pragma unroll
        for (int mt = 0; mt < 2; mt++)
            #pragma unroll
            for (int nt = 0; nt < 4; nt++)
                #pragma unroll
                for (int ks = 0; ks < 2; ks++)
                    mma16816(D[mt][nt], a[mt][ks], bb[nt][ks]);
    }

    // ---- scatter epilogue with bias ----
    #pragma unroll
    for (int mt = 0; mt < 2; mt++) {
        #pragma unroll
        for (int nt = 0; nt < 4; nt++) {
            int col = n0 + wn + nt * 8 + t2;
            float2 bv = *(const float2*)&bias[col];
            #pragma unroll
            for (int half = 0; half < 2; half++) {
                int mrow = m0 + wm + mt * 16 + g + half * 8;
                int wI = mrow >> 9, t = mrow & 511;
                int bI = wI >> 3, jI = wI & 7;
                int rI = t >> 3, c2I = t & 7;
                size_t o = ((size_t)bI * LTOK + rI * RESO + jI * 8 + c2I) * DIMC + col;
                float2 r;
                r.x = D[mt][nt][half * 2 + 0] + bv.x;
                r.y = D[mt][nt][half * 2 + 1] + bv.y;
                *(float2*)&out[o] = r;
            }
        }
    }
}

// ---------------------------------------------------------------------------
extern "C" void kernel_launch(void* const* d_in, const int* in_sizes, int n_in,
                              void* d_out, int out_size) {
    (void)in_sizes; (void)n_in; (void)out_size;
    const float* qkv    = (const float*)d_in[0];
    const float* scale  = (const float*)d_in[1];
    const float* proj_w = (const float*)d_in[2];
    const float* proj_b = (const float*)d_in[3];
    const float* conv_w = (const float*)d_in[4];
    const float* conv_b = (const float*)d_in[5];
    float* out = (float*)d_out;

    prep_fused<<<3104, 256>>>(qkv, proj_w, conv_w, conv_b);

    cudaFuncSetAttribute(attn_hmma, cudaFuncAttributeMaxDynamicSharedMemorySize,
                         ATTN_SMEM_BYTES);
    attn_hmma<<<dim3(NWTOT, NH, 2), 256, ATTN_SMEM_BYTES>>>(qkv, scale);

    cudaFuncSetAttribute(proj_hmma, cudaFuncAttributeMaxDynamicSharedMemorySize,
                         PROJ_SMEM_BYTES);
    proj_hmma<<<dim3(DIMC / 64, MROWS / 128), 256, PROJ_SMEM_BYTES>>>(proj_b, out);
}

// round 11
// speedup vs baseline: 13.8439x; 1.1084x over previous
#include <cuda_runtime.h>
#include <cuda_fp16.h>
#include <cstdint>

#define BATCH 8
#define RESO 64
#define DIMC 256
#define NH 8
#define HD 32
#define WIN 512
#define NWTOT 64
#define LTOK 4096
#define MROWS (NWTOT * WIN)          // 32768
#define PLANE ((size_t)MROWS * 40)   // halves per chunk-plane of g_xh

// ---------------------------------------------------------------------------
// Scratch (__device__ globals: allocation-free rule)
// ---------------------------------------------------------------------------
__device__ __align__(16) __half g_lepe[(size_t)MROWS * DIMC];
__device__ __align__(16) __half g_xh[(size_t)NH * PLANE];            // [chunk(=head)][row][40]
__device__ __align__(16) __half g_vt[(size_t)NWTOT * NH * 32 * 520]; // [w][n][d][520]
__device__ __align__(16) __half g_wh[(size_t)8 * DIMC * 40];         // [chunk][col][40]

// ---------------------------------------------------------------------------
// Helpers
// ---------------------------------------------------------------------------
__device__ __forceinline__ uint32_t packh2(float x, float y) {
    __half2 h = __floats2half2_rn(x, y);
    return *reinterpret_cast<uint32_t*>(&h);
}
__device__ __forceinline__ uint32_t smem_u32(const void* p) {
    uint32_t a;
    asm("{ .reg .u64 t; cvta.to.shared.u64 t, %1; cvt.u32.u64 %0, t; }"
        : "=r"(a) : "l"(p));
    return a;
}
__device__ __forceinline__ void mma16816(float d[4], const uint32_t a[4],
                                         const uint32_t b[2]) {
    asm volatile(
        "mma.sync.aligned.m16n8k16.row.col.f32.f16.f16.f32 "
        "{%0,%1,%2,%3}, {%4,%5,%6,%7}, {%8,%9}, {%0,%1,%2,%3};\n"
        : "+f"(d[0]), "+f"(d[1]), "+f"(d[2]), "+f"(d[3])
        : "r"(a[0]), "r"(a[1]), "r"(a[2]), "r"(a[3]), "r"(b[0]), "r"(b[1]));
}
#define LDSM_X4(r0, r1, r2, r3, addr) \
    asm volatile("ldmatrix.sync.aligned.m8n8.x4.shared.b16 {%0,%1,%2,%3}, [%4];" \
                 : "=r"(r0), "=r"(r1), "=r"(r2), "=r"(r3) : "r"(addr))
#define EX2F16X2(d, s) \
    asm("ex2.approx.f16x2 %0, %1;" : "=r"(d) : "r"(s))
#define CP_ASYNC16(dst, src) \
    asm volatile("cp.async.cg.shared.global [%0], [%1], 16;" :: "r"(dst), "l"(src))
#define CP_COMMIT() asm volatile("cp.async.commit_group;")

// ---------------------------------------------------------------------------
// Fused prep: region split by flat blockIdx.x
//   [0, 512)   lepe (depthwise 3x3 conv, fp16 out, slab of 8 rows)
//              + Vt fp16 emit with smem-staged coalesced writeback
//   [512, 544) prep_w: W fp32 -> fp16 [chunk][col][40]
// ---------------------------------------------------------------------------
__global__ __launch_bounds__(256) void prep_fused(const float* __restrict__ qkv,
                                                  const float* __restrict__ W,
                                                  const float* __restrict__ cw,
                                                  const float* __restrict__ cb) {
    __shared__ __half sbuf[256][72];   // [channel][64 keys + pad] (144B rows)
    const int bid = blockIdx.x, tid = threadIdx.x;

    if (bid < 512) {
        // ---- LePE + Vt (slab of 8 rows = 64 window tokens) ----
        const int slab = bid & 7, w = bid >> 3;
        const int c = tid;
        const int b = w >> 3, j = w & 7;
        const float* v = qkv + 2ULL * BATCH * LTOK * DIMC;
        float wt[9];
        #pragma unroll
        for (int i = 0; i < 9; i++) wt[i] = cw[c * 9 + i];
        const float bias = cb[c];
        const int r0 = slab * 8;
        const float* base = v + ((size_t)b * LTOK + j * 8) * DIMC + c;
        __half* outb = g_lepe + (size_t)w * WIN * DIMC + c;

        float rows[3][8];
        #pragma unroll
        for (int cc = 0; cc < 8; cc++) {
            rows[0][cc] = (r0 == 0) ? 0.f : base[((size_t)(r0 - 1) * RESO + cc) * DIMC];
            rows[1][cc] = base[((size_t)r0 * RESO + cc) * DIMC];
        }
        #pragma unroll
        for (int rr = 0; rr < 8; rr++) {
            const int prv = rr % 3, cur = (rr + 1) % 3, nxt = (rr + 2) % 3;
            const int rn = r0 + rr + 1;
            #pragma unroll
            for (int cc = 0; cc < 8; cc++)
                rows[nxt][cc] = (rn >= RESO) ? 0.f : base[((size_t)rn * RESO + cc) * DIMC];
            const int rabs = r0 + rr;
            // stage Vt row chunk in smem (16B aligned: rr*8 halves)
            {
                union { uint4 u; __half h[8]; } pk;
                #pragma unroll
                for (int cc = 0; cc < 8; cc++) pk.h[cc] = __float2half_rn(rows[cur][cc]);
                *(uint4*)(&sbuf[c][rr * 8]) = pk.u;
            }
            #pragma unroll
            for (int cc = 0; cc < 8; cc++) {
                float acc = bias;
                if (cc > 0) {
                    acc += rows[prv][cc - 1] * wt[0];
                    acc += rows[cur][cc - 1] * wt[3];
                    acc += rows[nxt][cc - 1] * wt[6];
                }
                acc += rows[prv][cc] * wt[1];
                acc += rows[cur][cc] * wt[4];
                acc += rows[nxt][cc] * wt[7];
                if (cc < 7) {
                    acc += rows[prv][cc + 1] * wt[2];
                    acc += rows[cur][cc + 1] * wt[5];
                    acc += rows[nxt][cc + 1] * wt[8];
                }
                outb[(size_t)(rabs * 8 + cc) * DIMC] = __float2half_rn(acc);
            }
        }
        __syncthreads();
        // ---- coalesced Vt writeback: 8 lanes cover one channel row (128B) ----
        #pragma unroll
        for (int it = 0; it < 8; it++) {
            int idx = tid + it * 256;          // 0..2047
            int row = idx >> 3, q = idx & 7;   // channel row, 16B quad
            int nn = row >> 5, dd = row & 31;
            uint4 val = *(const uint4*)(&sbuf[row][q * 8]);
            __half* dst = g_vt + ((size_t)(w * NH + nn) * 32 + dd) * 520 + slab * 64 + q * 8;
            *(uint4*)dst = val;
        }
    } else {
        // ---- prep_w (vectorized 8 floats -> uint4 of halves) ----
        const int gid = (bid - 512) * 256 + tid;   // 0..8191
        const int c = gid >> 5, k0 = (gid & 31) * 8;
        float4 w0 = *(const float4*)&W[(size_t)c * DIMC + k0];
        float4 w1 = *(const float4*)&W[(size_t)c * DIMC + k0 + 4];
        union { uint4 u; __half2 h[4]; } pk;
        pk.h[0] = __floats2half2_rn(w0.x, w0.y);
        pk.h[1] = __floats2half2_rn(w0.z, w0.w);
        pk.h[2] = __floats2half2_rn(w1.x, w1.y);
        pk.h[3] = __floats2half2_rn(w1.z, w1.w);
        *(uint4*)(g_wh + (size_t)(k0 >> 5) * (DIMC * 40) + c * 40 + (k0 & 31)) = pk.u;
    }
}

// ---------------------------------------------------------------------------
// HMMA flash attention. CTA = (window, head, half). 8 warps x 32 query rows.
// K converted fp32->fp16 in the fill (no prep_k round-trip). fp16 exp.
// smem: Kh [512][40] + Vt [32][520] = 72.5 KB -> 2 CTAs/SM.
// ---------------------------------------------------------------------------
#define VTOo (512 * 40)          // halves
#define VTOBYTES (512 * 40 * 2)
#define ATTN_SMEM_BYTES ((512 * 40 + 32 * 520) * 2)

__global__ __launch_bounds__(256, 2) void attn_hmma(const float* __restrict__ qkv,
                                                    const float* __restrict__ scale_p) {
    extern __shared__ __half sm[];
    const int tid = threadIdx.x;
    const int w = blockIdx.x, n = blockIdx.y, z = blockIdx.z;
    const int b = w >> 3, j = w & 7;
    const float qscale = scale_p[0] * 1.44269504f;
    const float* kp = qkv + (size_t)BATCH * LTOK * DIMC;

    // ---- fill K (convert fp32->fp16) & Vt (vector copy) ----
    #pragma unroll
    for (int it = 0; it < 16; it++) {
        int i = tid + it * 256;
        int s = i >> 3, f4 = i & 7;
        int rs = s >> 3, cs = s & 7;
        float4 kf = *(const float4*)(kp + ((size_t)b * LTOK + rs * RESO + j * 8 + cs) * DIMC
                                        + n * HD + f4 * 4);
        uint2 h;
        h.x = packh2(kf.x, kf.y);
        h.y = packh2(kf.z, kf.w);
        *(uint2*)(sm + s * 40 + f4 * 4) = h;
    }
    {
        const uint4* gv = (const uint4*)(g_vt + (size_t)(w * NH + n) * 32 * 520);
        uint4* dv = (uint4*)(sm + VTOo);
        #pragma unroll
        for (int i = 0; i < 8; i++) dv[tid + i * 256] = gv[tid + i * 256];
        if (tid < 2080 - 2048) dv[tid + 2048] = gv[tid + 2048];
    }

    const int wid = tid >> 5, lane = tid & 31;
    const int g = lane >> 2, t2 = (lane & 3) * 2;
    const int m0 = z * 256 + wid * 32;
    const bool mzero = (j == 7) && ((g < 4) != ((lane & 3) < 2));

    // ---- persistent Q fragments (2 m-tiles, fp16, scaled) ----
    uint32_t qh[2][2][4];
    #pragma unroll
    for (int mt = 0; mt < 2; mt++) {
        #pragma unroll
        for (int rh = 0; rh < 2; rh++) {
            int row = m0 + mt * 16 + g + rh * 8;
            int rs = row >> 3, cs = row & 7;
            const float* src = qkv + ((size_t)b * LTOK + rs * RESO + j * 8 + cs) * DIMC + n * HD;
            #pragma unroll
            for (int ks = 0; ks < 2; ks++) {
                #pragma unroll
                for (int ch = 0; ch < 2; ch++) {
                    float2 f = *(const float2*)(src + ks * 16 + ch * 8 + t2);
                    qh[mt][ks][rh + ch * 2] = packh2(f.x * qscale, f.y * qscale);
                }
            }
        }
    }
    __syncthreads();

    const uint32_t sb = smem_u32(sm);
    const uint32_t kconst = sb + (uint32_t)((lane & 7) * 80 + (lane >> 3) * 16);
    const uint32_t vconst = sb + VTOBYTES +
        (uint32_t)((((lane >> 4) * 8) + (lane & 7)) * 1040 + ((lane >> 3) & 1) * 16);

    float O[2][4][4];
    float lsl[2] = {0.f, 0.f}, lsh[2] = {0.f, 0.f};
    #pragma unroll
    for (int mt = 0; mt < 2; mt++)
        #pragma unroll
        for (int nt = 0; nt < 4; nt++)
            #pragma unroll
            for (int e = 0; e < 4; e++) O[mt][nt][e] = 0.f;

    #pragma unroll 4
    for (int step = 0; step < 32; step++) {
        float S[2][2][4];
        #pragma unroll
        for (int mt = 0; mt < 2; mt++)
            #pragma unroll
            for (int nt = 0; nt < 2; nt++)
                #pragma unroll
                for (int e = 0; e < 4; e++) S[mt][nt][e] = 0.f;

        uint32_t kb[2][2][2];
        LDSM_X4(kb[0][0][0], kb[0][0][1], kb[0][1][0], kb[0][1][1],
                kconst + (uint32_t)step * 1280u);
        LDSM_X4(kb[1][0][0], kb[1][0][1], kb[1][1][0], kb[1][1][1],
                kconst + (uint32_t)step * 1280u + 640u);
        #pragma unroll
        for (int mt = 0; mt < 2; mt++)
            #pragma unroll
            for (int nt = 0; nt < 2; nt++)
                #pragma unroll
                for (int ks = 0; ks < 2; ks++)
                    mma16816(S[mt][nt], qh[mt][ks], kb[nt][ks]);

        // ---- softmax: pack S -> fp16x2, ex2 in fp16; lsum via HADD2+fp32 ----
        uint32_t pa[2][4];
        #pragma unroll
        for (int mt = 0; mt < 2; mt++) {
            #pragma unroll
            for (int nt = 0; nt < 2; nt++) {
                uint32_t s01 = packh2(S[mt][nt][0], S[mt][nt][1]);
                uint32_t s23 = packh2(S[mt][nt][2], S[mt][nt][3]);
                uint32_t p01, p23;
                EX2F16X2(p01, s01);
                EX2F16X2(p23, s23);
                pa[mt][nt * 2 + 0] = mzero ? 0u : p01;
                pa[mt][nt * 2 + 1] = mzero ? 0u : p23;
            }
            __half2 tl = __hadd2(*(__half2*)&pa[mt][0], *(__half2*)&pa[mt][2]);
            __half2 th = __hadd2(*(__half2*)&pa[mt][1], *(__half2*)&pa[mt][3]);
            float2 fl = __half22float2(tl);
            float2 fh = __half22float2(th);
            lsl[mt] += fl.x + fl.y;
            lsh[mt] += fh.x + fh.y;
        }

        uint32_t vb[4][2];
        LDSM_X4(vb[0][0], vb[0][1], vb[1][0], vb[1][1],
                vconst + (uint32_t)step * 32u);
        LDSM_X4(vb[2][0], vb[2][1], vb[3][0], vb[3][1],
                vconst + (uint32_t)step * 32u + 16640u);
        #pragma unroll
        for (int mt = 0; mt < 2; mt++)
            #pragma unroll
            for (int ntd = 0; ntd < 4; ntd++)
                mma16816(O[mt][ntd], pa[mt], vb[ntd]);
    }

    // ---- quad reduction of row sums ----
    #pragma unroll
    for (int mt = 0; mt < 2; mt++) {
        lsl[mt] += __shfl_xor_sync(0xffffffffu, lsl[mt], 1);
        lsl[mt] += __shfl_xor_sync(0xffffffffu, lsl[mt], 2);
        lsh[mt] += __shfl_xor_sync(0xffffffffu, lsh[mt], 1);
        lsh[mt] += __shfl_xor_sync(0xffffffffu, lsh[mt], 2);
    }

    // ---- epilogue: O/lsum + lepe(fp16) -> fp16 chunk-major padded g_xh ----
    #pragma unroll
    for (int mt = 0; mt < 2; mt++) {
        const float il = 1.f / lsl[mt];
        const float ih = 1.f / lsh[mt];
        const int r0q = m0 + mt * 16 + g;
        const size_t grow = (size_t)w * WIN + r0q;
        #pragma unroll
        for (int ntd = 0; ntd < 4; ntd++) {
            size_t l0 = grow * DIMC + n * HD + ntd * 8 + t2;
            size_t l1 = l0 + 8 * DIMC;
            size_t x0 = (size_t)n * PLANE + grow * 40 + ntd * 8 + t2;
            size_t x1 = x0 + 8 * 40;
            float2 e0 = __half22float2(*(const __half2*)(g_lepe + l0));
            float2 e1 = __half22float2(*(const __half2*)(g_lepe + l1));
            *(__half2*)(g_xh + x0) = __floats2half2_rn(O[mt][ntd][0] * il + e0.x,
                                                       O[mt][ntd][1] * il + e0.y);
            *(__half2*)(g_xh + x1) = __floats2half2_rn(O[mt][ntd][2] * ih + e1.x,
                                                       O[mt][ntd][3] * ih + e1.y);
        }
    }
}

// ---------------------------------------------------------------------------
// Projection: out = x @ W^T + b. CTA 128m x 64n, 8 warps (4m x 2n) 32x32 tiles.
// cp.async 3-stage pipeline, one sync/chunk, ldmatrix fragments, 3 CTAs/SM.
// ---------------------------------------------------------------------------
#define PROJ_SMEM_BYTES (3 * (128 * 40 + 64 * 40) * 2)   // 46080

__global__ __launch_bounds__(256, 3) void proj_hmma(const float* __restrict__ bias,
                                                    float* __restrict__ out) {
    extern __shared__ __half psm[];
    const int tid = threadIdx.x;
    const int m0 = blockIdx.y * 128, n0 = blockIdx.x * 64;
    const int wid = tid >> 5, lane = tid & 31;
    const int g = lane >> 2, t2 = (lane & 3) * 2;
    const int wm = (wid >> 1) * 32, wn = (wid & 1) * 32;
    const uint32_t sb = smem_u32(psm);

    auto fill = [&](int c) {
        int s = c % 3;
        uint32_t abase = sb + (uint32_t)s * 10240u;
        const __half* asrc = g_xh + (size_t)c * PLANE + (size_t)m0 * 40;
        #pragma unroll
        for (int i = 0; i < 3; i++) {
            int idx = tid + i * 256;
            if (idx < 640) CP_ASYNC16(abase + idx * 16, asrc + idx * 8);
        }
        uint32_t bbase = sb + 30720u + (uint32_t)s * 5120u;
        const __half* bsrc = g_wh + (size_t)c * (DIMC * 40) + (size_t)n0 * 40;
        #pragma unroll
        for (int i = 0; i < 2; i++) {
            int idx = tid + i * 256;
            if (idx < 320) CP_ASYNC16(bbase + idx * 16, bsrc + idx * 8);
        }
        CP_COMMIT();
    };

    float D[2][4][4];
    #pragma unroll
    for (int mt = 0; mt < 2; mt++)
        #pragma unroll
        for (int nt = 0; nt < 4; nt++)
            #pragma unroll
            for (int e = 0; e < 4; e++) D[mt][nt][e] = 0.f;

    fill(0); fill(1);

    const uint32_t aoff = (uint32_t)(wm * 80 + (lane & 15) * 80 + (lane >> 4) * 16);
    const uint32_t boff = (uint32_t)(30720 + (wn + (lane & 7)) * 80 + (lane >> 3) * 16);

    #pragma unroll
    for (int c = 0; c < 8; c++) {
        if (c < 7) asm volatile("cp.async.wait_group 1;");
        else       asm volatile("cp.async.wait_group 0;");
        __syncthreads();
        if (c + 2 < 8) fill(c + 2);

        const uint32_t aconst = sb + (uint32_t)(c % 3) * 10240u + aoff;
        const uint32_t bconst = sb + (uint32_t)(c % 3) * 5120u + boff;

        uint32_t a[2][2][4];
        #pragma unroll
        for (int mt = 0; mt < 2; mt++)
            #pragma unroll
            for (int ks = 0; ks < 2; ks++)
                LDSM_X4(a[mt][ks][0], a[mt][ks][1], a[mt][ks][2], a[mt][ks][3],
                        aconst + (uint32_t)(mt * 1280 + ks * 32));
        uint32_t bb[4][2][2];
        #pragma unroll
        for (int nt = 0; nt < 4; nt++)
            LDSM_X4(bb[nt][0][0], bb[nt][0][1], bb[nt][1][0], bb[nt][1][1],
                    bconst + (uint32_t)(nt * 640));
        #pragma unroll
        for (int mt = 0; mt < 2; mt++)
            #pragma unroll
            for (int nt = 0; nt < 4; nt++)
                #pragma unroll
                for (int ks = 0; ks < 2; ks++)
                    mma16816(D[mt][nt], a[mt][ks], bb[nt][ks]);
    }

    // ---- scatter epilogue with bias ----
    #pragma unroll
    for (int mt = 0; mt < 2; mt++) {
        #pragma unroll
        for (int nt = 0; nt < 4; nt++) {
            int col = n0 + wn + nt * 8 + t2;
            float2 bv = *(const float2*)&bias[col];
            #pragma unroll
            for (int half = 0; half < 2; half++) {
                int mrow = m0 + wm + mt * 16 + g + half * 8;
                int wI = mrow >> 9, t = mrow & 511;
                int bI = wI >> 3, jI = wI & 7;
                int rI = t >> 3, c2I = t & 7;
                size_t o = ((size_t)bI * LTOK + rI * RESO + jI * 8 + c2I) * DIMC + col;
                float2 r;
                r.x = D[mt][nt][half * 2 + 0] + bv.x;
                r.y = D[mt][nt][half * 2 + 1] + bv.y;
                *(float2*)&out[o] = r;
            }
        }
    }
}

// ---------------------------------------------------------------------------
extern "C" void kernel_launch(void* const* d_in, const int* in_sizes, int n_in,
                              void* d_out, int out_size) {
    (void)in_sizes; (void)n_in; (void)out_size;
    const float* qkv    = (const float*)d_in[0];
    const float* scale  = (const float*)d_in[1];
    const float* proj_w = (const float*)d_in[2];
    const float* proj_b = (const float*)d_in[3];
    const float* conv_w = (const float*)d_in[4];
    const float* conv_b = (const float*)d_in[5];
    float* out = (float*)d_out;

    prep_fused<<<544, 256>>>(qkv, proj_w, conv_w, conv_b);

    cudaFuncSetAttribute(attn_hmma, cudaFuncAttributeMaxDynamicSharedMemorySize,
                         ATTN_SMEM_BYTES);
    attn_hmma<<<dim3(NWTOT, NH, 2), 256, ATTN_SMEM_BYTES>>>(qkv, scale);

    cudaFuncSetAttribute(proj_hmma, cudaFuncAttributeMaxDynamicSharedMemorySize,
                         PROJ_SMEM_BYTES);
    proj_hmma<<<dim3(DIMC / 64, MROWS / 128), 256, PROJ_SMEM_BYTES>>>(proj_b, out);
}